// round 1
// baseline (speedup 1.0000x reference)
#include <cuda_runtime.h>
#include <math.h>

#define HID  2048
#define B_   4
#define S_   4096
#define H_   16
#define P_   256
#define D_   128
#define N_   16
#define NT   1024        // B*H*N attention tiles
#define MTOK 16384       // B*S rows
#define SCALE 0.08838834764831845f   // 1/sqrt(128)

// ---------------- scratch (static device globals; no allocation allowed) ----
__device__ float g_q  [B_*S_*HID];      // 134 MB
__device__ float g_k  [B_*S_*HID];
__device__ float g_v  [B_*S_*HID];
__device__ float g_qp [NT*P_*D_];       // paged Q  [t][p2][d2]
__device__ float g_kp [NT*P_*D_];       // paged K  [t][k2][d2]
__device__ float g_vpt[NT*D_*P_];       // paged V^T [t][d2][k2]
__device__ float g_sc [NT*P_*P_];       // scores/probs [t][p2][k2]  268 MB
__device__ float g_ct [NT*P_*D_];       // ctx tiles [t][p2][d2]
__device__ float g_ca [B_*S_*HID];      // ctx arranged (B,S,HID)

// ---------------- generic C = alpha * A @ B^T (+bias), batched --------------
// A: M x K row-major (lda), B: N x K row-major (ldb), C: M x N (ldc)
// BM=BN=128, BK=16, 256 threads, 8x8 per thread.
__global__ __launch_bounds__(256, 2)
void gemm_abt(const float* __restrict__ A, const float* __restrict__ Bm,
              const float* __restrict__ bias, float* __restrict__ C,
              int M, int N, int K, int lda, int ldb, int ldc,
              long sA, long sB, long sC, float alpha)
{
    __shared__ float As[16][128];
    __shared__ float Bs[16][128];

    const int bz = blockIdx.z;
    A  += (long)bz * sA;
    Bm += (long)bz * sB;
    C  += (long)bz * sC;

    const int m0 = blockIdx.y * 128;
    const int n0 = blockIdx.x * 128;
    const int tid = threadIdx.x;
    const int tx = tid & 15;     // col group  -> n
    const int ty = tid >> 4;     // row group  -> m

    float acc[8][8];
#pragma unroll
    for (int i = 0; i < 8; i++)
#pragma unroll
        for (int j = 0; j < 8; j++) acc[i][j] = 0.f;

    for (int kt = 0; kt < K; kt += 16) {
#pragma unroll
        for (int u = 0; u < 2; u++) {
            int id = tid + u * 256;          // 0..511
            int r  = id >> 2;                // 0..127 tile row
            int c4 = (id & 3) << 2;          // 0,4,8,12
            float4 a = *(const float4*)(A + (long)(m0 + r) * lda + kt + c4);
            As[c4 + 0][r] = a.x; As[c4 + 1][r] = a.y;
            As[c4 + 2][r] = a.z; As[c4 + 3][r] = a.w;
            float4 b = *(const float4*)(Bm + (long)(n0 + r) * ldb + kt + c4);
            Bs[c4 + 0][r] = b.x; Bs[c4 + 1][r] = b.y;
            Bs[c4 + 2][r] = b.z; Bs[c4 + 3][r] = b.w;
        }
        __syncthreads();

#pragma unroll
        for (int k = 0; k < 16; k++) {
            float ar[8], br[8];
            *(float4*)(ar)     = *(const float4*)&As[k][ty * 8];
            *(float4*)(ar + 4) = *(const float4*)&As[k][ty * 8 + 4];
            *(float4*)(br)     = *(const float4*)&Bs[k][tx * 8];
            *(float4*)(br + 4) = *(const float4*)&Bs[k][tx * 8 + 4];
#pragma unroll
            for (int i = 0; i < 8; i++)
#pragma unroll
                for (int j = 0; j < 8; j++)
                    acc[i][j] += ar[i] * br[j];
        }
        __syncthreads();
    }

#pragma unroll
    for (int i = 0; i < 8; i++) {
        int row = m0 + ty * 8 + i;
#pragma unroll
        for (int j4 = 0; j4 < 8; j4 += 4) {
            float4 v;
            int col = n0 + tx * 8 + j4;
            float b0 = 0.f, b1 = 0.f, b2 = 0.f, b3 = 0.f;
            if (bias) { b0 = bias[col]; b1 = bias[col+1]; b2 = bias[col+2]; b3 = bias[col+3]; }
            v.x = alpha * acc[i][j4 + 0] + b0;
            v.y = alpha * acc[i][j4 + 1] + b1;
            v.z = alpha * acc[i][j4 + 2] + b2;
            v.w = alpha * acc[i][j4 + 3] + b3;
            *(float4*)(C + (long)row * ldc + col) = v;
        }
    }
}

// ---------------- repack Q/K into paged layout (transpose via smem) ---------
// paged[t][p2=2d+j][d2=r] = heads[b,h, n*256 + j*128 + r, d]
//   where heads[b,h,s,d] = proj[(b*S+s)*HID + h*128 + d], t = (b*16+h)*16+n
// grid (4,4,2048): z = ((b*16+h)*16+n)*2 + j ; block (32,8)
__global__ void repack_qk(const float* __restrict__ in, float* __restrict__ out)
{
    __shared__ float tile[32][33];
    const int bz = blockIdx.z;
    const int j = bz & 1, n = (bz >> 1) & 15, h = (bz >> 5) & 15, b = bz >> 9;
    const float* ib = in + ((long)(b * S_ + n * 256 + j * 128)) * HID + h * 128;
    float* ob = out + (long)((b * 16 + h) * 16 + n) * (P_ * D_);
    const int d0 = blockIdx.x * 32, r0 = blockIdx.y * 32;
    const int tx = threadIdx.x, ty = threadIdx.y;
#pragma unroll
    for (int i = 0; i < 32; i += 8)
        tile[ty + i][tx] = ib[(long)(r0 + ty + i) * HID + d0 + tx];   // coalesced read
    __syncthreads();
#pragma unroll
    for (int i = 0; i < 32; i += 8)
        ob[(long)(2 * (d0 + ty + i) + j) * D_ + r0 + tx] = tile[tx][ty + i]; // coalesced write
}

// ---------------- repack V transposed: vpt[t][d2=r][k2=2d+j] ----------------
// grid (64, 2048): y = bhnj ; block 256 (2 r-rows per block)
__global__ void repack_v(const float* __restrict__ in, float* __restrict__ out)
{
    const int bz = blockIdx.y;
    const int j = bz & 1, n = (bz >> 1) & 15, h = (bz >> 5) & 15, b = bz >> 9;
    const int idx = blockIdx.x * 256 + threadIdx.x;   // 0..16383 over (r,d)
    const int r = idx >> 7, d = idx & 127;
    const float* ib = in + ((long)(b * S_ + n * 256 + j * 128)) * HID + h * 128;
    long t = (b * 16 + h) * 16 + n;
    out[t * (long)(D_ * P_) + (long)r * P_ + 2 * d + j] = ib[(long)r * HID + d];
}

// ---------------- softmax over rows of 256 (1 warp per row) -----------------
__global__ void softmax_rows(float* __restrict__ Smat)
{
    const int warp = (blockIdx.x * blockDim.x + threadIdx.x) >> 5;
    const int lane = threadIdx.x & 31;
    float* row = Smat + (long)warp * 256;
    float v[8];
    float mx = -1e30f;
#pragma unroll
    for (int i = 0; i < 8; i++) { v[i] = row[lane + i * 32]; mx = fmaxf(mx, v[i]); }
#pragma unroll
    for (int o = 16; o; o >>= 1) mx = fmaxf(mx, __shfl_xor_sync(~0u, mx, o));
    float s = 0.f;
#pragma unroll
    for (int i = 0; i < 8; i++) { v[i] = __expf(v[i] - mx); s += v[i]; }
#pragma unroll
    for (int o = 16; o; o >>= 1) s += __shfl_xor_sync(~0u, s, o);
    const float inv = 1.f / s;
#pragma unroll
    for (int i = 0; i < 8; i++) row[lane + i * 32] = v[i] * inv;
}

// ---------------- ctx tiles -> (B,S,HID) arrangement ------------------------
// out[(b*4096 + h*256 + p2)*HID + n*128 + d2] = ct[t][p2][d2]
__global__ void rearrange_ctx(const float* __restrict__ in, float* __restrict__ out)
{
    const long t = blockIdx.y;
    const int b = (int)(t >> 8), h = (int)((t >> 4) & 15), n = (int)(t & 15);
    const int idx = blockIdx.x * 256 + threadIdx.x;   // p2*128 + d2
    const int p2 = idx >> 7, d2 = idx & 127;
    out[((long)(b * 4096 + h * 256 + p2)) * HID + n * 128 + d2] = in[t * 32768 + idx];
}

// ---------------- launch ------------------------------------------------------
extern "C" void kernel_launch(void* const* d_in, const int* in_sizes, int n_in,
                              void* d_out, int out_size)
{
    const float* X  = (const float*)d_in[0];
    const float* Wq = (const float*)d_in[1];
    const float* bq = (const float*)d_in[2];
    const float* Wk = (const float*)d_in[3];
    const float* bk = (const float*)d_in[4];
    const float* Wv = (const float*)d_in[5];
    const float* bv = (const float*)d_in[6];
    const float* Wo = (const float*)d_in[7];
    const float* bo = (const float*)d_in[8];
    float* out = (float*)d_out;

    float *q, *k, *v, *qp, *kp, *vpt, *sc, *ct, *ca;
    cudaGetSymbolAddress((void**)&q,   g_q);
    cudaGetSymbolAddress((void**)&k,   g_k);
    cudaGetSymbolAddress((void**)&v,   g_v);
    cudaGetSymbolAddress((void**)&qp,  g_qp);
    cudaGetSymbolAddress((void**)&kp,  g_kp);
    cudaGetSymbolAddress((void**)&vpt, g_vpt);
    cudaGetSymbolAddress((void**)&sc,  g_sc);
    cudaGetSymbolAddress((void**)&ct,  g_ct);
    cudaGetSymbolAddress((void**)&ca,  g_ca);

    dim3 gProj(HID / 128, MTOK / 128, 1);   // 16 x 128
    // QKV projections: C = X @ W^T + b
    gemm_abt<<<gProj, 256>>>(X, Wq, bq, q, MTOK, HID, HID, HID, HID, HID, 0, 0, 0, 1.f);
    gemm_abt<<<gProj, 256>>>(X, Wk, bk, k, MTOK, HID, HID, HID, HID, HID, 0, 0, 0, 1.f);
    gemm_abt<<<gProj, 256>>>(X, Wv, bv, v, MTOK, HID, HID, HID, HID, HID, 0, 0, 0, 1.f);

    // repack into paged layout
    repack_qk<<<dim3(4, 4, 2048), dim3(32, 8)>>>(q, qp);
    repack_qk<<<dim3(4, 4, 2048), dim3(32, 8)>>>(k, kp);
    repack_v <<<dim3(64, 2048), 256>>>(v, vpt);

    // scores = SCALE * Qp @ Kp^T  (batched over 1024 tiles)
    gemm_abt<<<dim3(2, 2, NT), 256>>>(qp, kp, nullptr, sc,
                                      P_, P_, D_, D_, D_, P_,
                                      (long)P_ * D_, (long)P_ * D_, (long)P_ * P_, SCALE);

    // softmax over 1024*256 rows
    softmax_rows<<<NT * 256 / 8, 256>>>(sc);

    // ctx = probs @ Vp   (== probs @ (Vp^T)^T, batched)
    gemm_abt<<<dim3(1, 2, NT), 256>>>(sc, vpt, nullptr, ct,
                                      P_, D_, P_, P_, P_, D_,
                                      (long)P_ * P_, (long)D_ * P_, (long)P_ * D_, 1.f);

    // arrange ctx back to (B, S, HID)
    rearrange_ctx<<<dim3(128, NT), 256>>>(ct, ca);

    // output projection
    gemm_abt<<<gProj, 256>>>(ca, Wo, bo, out, MTOK, HID, HID, HID, HID, HID, 0, 0, 0, 1.f);
}

// round 2
// speedup vs baseline: 3.2628x; 3.2628x over previous
#include <cuda_runtime.h>
#include <math.h>
#include <stdint.h>

#define HID  2048
#define B_   4
#define S_   4096
#define H_   16
#define P_   256
#define D_   128
#define N_   16
#define NT   1024        // B*H*N attention tiles
#define MTOK 16384       // B*S rows
#define SCALE 0.08838834764831845f   // 1/sqrt(128)

// ---------------- scratch (static device globals; no allocation allowed) ----
__device__ float g_q  [B_*S_*HID];
__device__ float g_k  [B_*S_*HID];
__device__ float g_v  [B_*S_*HID];
__device__ float g_qp [NT*P_*D_];       // paged Q  [t][p2][d2]
__device__ float g_kp [NT*P_*D_];       // paged K  [t][k2][d2]
__device__ float g_vpt[NT*D_*P_];       // paged V^T [t][d2][k2]
__device__ float g_sc [NT*P_*P_];       // scores/probs [t][p2][k2]
__device__ float g_ct [NT*P_*D_];       // ctx tiles [t][p2][d2]
__device__ float g_ca [B_*S_*HID];      // ctx arranged (B,S,HID)

// ---------------- TF32 tensor-core GEMM: C = alpha * A @ B^T (+bias) --------
// A: M x K row-major (lda), B: N x K row-major (ldb), C: M x N (ldc), batched z.
// BM=BN=128, BK=32, 256 threads (8 warps: 2x4), warp tile 64x32,
// mma.sync.m16n8k8.tf32, cp.async double-buffered smem (padded rows of 36).
#define PAD 36
#define SMEM_FLOATS (2 * 2 * 128 * PAD)      // 2 bufs x (As+Bs) x 128 rows
#define SMEM_BYTES  (SMEM_FLOATS * 4)        // 73728

__device__ __forceinline__ uint32_t f2tf32(float f) {
    uint32_t u;
    asm("cvt.rna.tf32.f32 %0, %1;" : "=r"(u) : "f"(f));
    return u;
}

__global__ __launch_bounds__(256, 2)
void gemm_tf32(const float* __restrict__ A, const float* __restrict__ Bm,
               const float* __restrict__ bias, float* __restrict__ C,
               int M, int N, int K, int lda, int ldb, int ldc,
               long sA, long sB, long sC, float alpha)
{
    extern __shared__ float smem[];
    float* As = smem;                         // [2][128][PAD]
    float* Bs = smem + 2 * 128 * PAD;         // [2][128][PAD]

    const int bz = blockIdx.z;
    A  += (long)bz * sA;
    Bm += (long)bz * sB;
    C  += (long)bz * sC;

    const int m0 = blockIdx.y * 128;
    const int n0 = blockIdx.x * 128;
    const int tid  = threadIdx.x;
    const int lane = tid & 31;
    const int wid  = tid >> 5;
    const int wm   = wid >> 2;          // 0..1  -> 64-row slab
    const int wn   = wid & 3;           // 0..3  -> 32-col slab
    const int g    = lane >> 2;         // groupID 0..7
    const int tg   = lane & 3;          // 0..3

    float acc[4][4][4];
#pragma unroll
    for (int i = 0; i < 4; i++)
#pragma unroll
        for (int j = 0; j < 4; j++)
#pragma unroll
            for (int r = 0; r < 4; r++) acc[i][j][r] = 0.f;

    const int nK = K >> 5;   // K / 32 tiles

    // prefetch one BK=32 tile of A and B into buffer buf
    auto prefetch = [&](int kt, int buf) {
#pragma unroll
        for (int u = 0; u < 4; u++) {
            int c    = tid + u * 256;        // 0..1023
            int row  = c >> 3;               // 0..127
            int col4 = (c & 7) << 2;         // 0,4,...,28
            const float* ga = A  + (long)(m0 + row) * lda + kt * 32 + col4;
            const float* gb = Bm + (long)(n0 + row) * ldb + kt * 32 + col4;
            uint32_t da = (uint32_t)__cvta_generic_to_shared(
                              &As[(buf * 128 + row) * PAD + col4]);
            uint32_t db = (uint32_t)__cvta_generic_to_shared(
                              &Bs[(buf * 128 + row) * PAD + col4]);
            asm volatile("cp.async.cg.shared.global [%0], [%1], 16;" :: "r"(da), "l"(ga));
            asm volatile("cp.async.cg.shared.global [%0], [%1], 16;" :: "r"(db), "l"(gb));
        }
        asm volatile("cp.async.commit_group;");
    };

    prefetch(0, 0);

    for (int t = 0; t < nK; t++) {
        if (t + 1 < nK) {
            prefetch(t + 1, (t + 1) & 1);
            asm volatile("cp.async.wait_group 1;");
        } else {
            asm volatile("cp.async.wait_group 0;");
        }
        __syncthreads();

        const float* Ab = &As[(t & 1) * 128 * PAD];
        const float* Bb = &Bs[(t & 1) * 128 * PAD];

#pragma unroll
        for (int k0 = 0; k0 < 32; k0 += 8) {
            uint32_t af[4][4], bf[4][2];
#pragma unroll
            for (int mi = 0; mi < 4; mi++) {
                int r0 = wm * 64 + mi * 16 + g;
                af[mi][0] = f2tf32(Ab[(r0    ) * PAD + k0 + tg    ]);
                af[mi][1] = f2tf32(Ab[(r0 + 8) * PAD + k0 + tg    ]);
                af[mi][2] = f2tf32(Ab[(r0    ) * PAD + k0 + tg + 4]);
                af[mi][3] = f2tf32(Ab[(r0 + 8) * PAD + k0 + tg + 4]);
            }
#pragma unroll
            for (int ni = 0; ni < 4; ni++) {
                int c0 = wn * 32 + ni * 8 + g;
                bf[ni][0] = f2tf32(Bb[c0 * PAD + k0 + tg    ]);
                bf[ni][1] = f2tf32(Bb[c0 * PAD + k0 + tg + 4]);
            }
#pragma unroll
            for (int mi = 0; mi < 4; mi++)
#pragma unroll
                for (int ni = 0; ni < 4; ni++) {
                    asm volatile(
                        "mma.sync.aligned.m16n8k8.row.col.f32.tf32.tf32.f32 "
                        "{%0,%1,%2,%3}, {%4,%5,%6,%7}, {%8,%9}, {%0,%1,%2,%3};"
                        : "+f"(acc[mi][ni][0]), "+f"(acc[mi][ni][1]),
                          "+f"(acc[mi][ni][2]), "+f"(acc[mi][ni][3])
                        : "r"(af[mi][0]), "r"(af[mi][1]),
                          "r"(af[mi][2]), "r"(af[mi][3]),
                          "r"(bf[ni][0]), "r"(bf[ni][1]));
                }
        }
        __syncthreads();
    }

    // epilogue
#pragma unroll
    for (int mi = 0; mi < 4; mi++) {
#pragma unroll
        for (int ni = 0; ni < 4; ni++) {
            int row = m0 + wm * 64 + mi * 16 + g;
            int col = n0 + wn * 32 + ni * 8 + 2 * tg;
            float b0 = 0.f, b1 = 0.f;
            if (bias) { b0 = bias[col]; b1 = bias[col + 1]; }
            float2 v0, v1;
            v0.x = alpha * acc[mi][ni][0] + b0;
            v0.y = alpha * acc[mi][ni][1] + b1;
            v1.x = alpha * acc[mi][ni][2] + b0;
            v1.y = alpha * acc[mi][ni][3] + b1;
            *(float2*)(C + (long)row * ldc + col)       = v0;
            *(float2*)(C + (long)(row + 8) * ldc + col) = v1;
        }
    }
}

// ---------------- repack Q/K into paged layout (transpose via smem) ---------
__global__ void repack_qk(const float* __restrict__ in, float* __restrict__ out)
{
    __shared__ float tile[32][33];
    const int bz = blockIdx.z;
    const int j = bz & 1, n = (bz >> 1) & 15, h = (bz >> 5) & 15, b = bz >> 9;
    const float* ib = in + ((long)(b * S_ + n * 256 + j * 128)) * HID + h * 128;
    float* ob = out + (long)((b * 16 + h) * 16 + n) * (P_ * D_);
    const int d0 = blockIdx.x * 32, r0 = blockIdx.y * 32;
    const int tx = threadIdx.x, ty = threadIdx.y;
#pragma unroll
    for (int i = 0; i < 32; i += 8)
        tile[ty + i][tx] = ib[(long)(r0 + ty + i) * HID + d0 + tx];
    __syncthreads();
#pragma unroll
    for (int i = 0; i < 32; i += 8)
        ob[(long)(2 * (d0 + ty + i) + j) * D_ + r0 + tx] = tile[tx][ty + i];
}

// ---------------- repack V transposed: vpt[t][d2=r][k2=2d+j] ----------------
__global__ void repack_v(const float* __restrict__ in, float* __restrict__ out)
{
    const int bz = blockIdx.y;
    const int j = bz & 1, n = (bz >> 1) & 15, h = (bz >> 5) & 15, b = bz >> 9;
    const int idx = blockIdx.x * 256 + threadIdx.x;
    const int r = idx >> 7, d = idx & 127;
    const float* ib = in + ((long)(b * S_ + n * 256 + j * 128)) * HID + h * 128;
    long t = (b * 16 + h) * 16 + n;
    out[t * (long)(D_ * P_) + (long)r * P_ + 2 * d + j] = ib[(long)r * HID + d];
}

// ---------------- softmax over rows of 256 (1 warp per row) -----------------
__global__ void softmax_rows(float* __restrict__ Smat)
{
    const int warp = (blockIdx.x * blockDim.x + threadIdx.x) >> 5;
    const int lane = threadIdx.x & 31;
    float* row = Smat + (long)warp * 256;
    float v[8];
    float mx = -1e30f;
#pragma unroll
    for (int i = 0; i < 8; i++) { v[i] = row[lane + i * 32]; mx = fmaxf(mx, v[i]); }
#pragma unroll
    for (int o = 16; o; o >>= 1) mx = fmaxf(mx, __shfl_xor_sync(~0u, mx, o));
    float s = 0.f;
#pragma unroll
    for (int i = 0; i < 8; i++) { v[i] = __expf(v[i] - mx); s += v[i]; }
#pragma unroll
    for (int o = 16; o; o >>= 1) s += __shfl_xor_sync(~0u, s, o);
    const float inv = 1.f / s;
#pragma unroll
    for (int i = 0; i < 8; i++) row[lane + i * 32] = v[i] * inv;
}

// ---------------- ctx tiles -> (B,S,HID) arrangement ------------------------
__global__ void rearrange_ctx(const float* __restrict__ in, float* __restrict__ out)
{
    const long t = blockIdx.y;
    const int b = (int)(t >> 8), h = (int)((t >> 4) & 15), n = (int)(t & 15);
    const int idx = blockIdx.x * 256 + threadIdx.x;
    const int p2 = idx >> 7, d2 = idx & 127;
    out[((long)(b * 4096 + h * 256 + p2)) * HID + n * 128 + d2] = in[t * 32768 + idx];
}

// ---------------- launch ------------------------------------------------------
extern "C" void kernel_launch(void* const* d_in, const int* in_sizes, int n_in,
                              void* d_out, int out_size)
{
    const float* X  = (const float*)d_in[0];
    const float* Wq = (const float*)d_in[1];
    const float* bq = (const float*)d_in[2];
    const float* Wk = (const float*)d_in[3];
    const float* bk = (const float*)d_in[4];
    const float* Wv = (const float*)d_in[5];
    const float* bv = (const float*)d_in[6];
    const float* Wo = (const float*)d_in[7];
    const float* bo = (const float*)d_in[8];
    float* out = (float*)d_out;

    float *q, *k, *v, *qp, *kp, *vpt, *sc, *ct, *ca;
    cudaGetSymbolAddress((void**)&q,   g_q);
    cudaGetSymbolAddress((void**)&k,   g_k);
    cudaGetSymbolAddress((void**)&v,   g_v);
    cudaGetSymbolAddress((void**)&qp,  g_qp);
    cudaGetSymbolAddress((void**)&kp,  g_kp);
    cudaGetSymbolAddress((void**)&vpt, g_vpt);
    cudaGetSymbolAddress((void**)&sc,  g_sc);
    cudaGetSymbolAddress((void**)&ct,  g_ct);
    cudaGetSymbolAddress((void**)&ca,  g_ca);

    cudaFuncSetAttribute(gemm_tf32, cudaFuncAttributeMaxDynamicSharedMemorySize,
                         SMEM_BYTES);

    dim3 gProj(HID / 128, MTOK / 128, 1);   // 16 x 128
    gemm_tf32<<<gProj, 256, SMEM_BYTES>>>(X, Wq, bq, q, MTOK, HID, HID, HID, HID, HID, 0, 0, 0, 1.f);
    gemm_tf32<<<gProj, 256, SMEM_BYTES>>>(X, Wk, bk, k, MTOK, HID, HID, HID, HID, HID, 0, 0, 0, 1.f);
    gemm_tf32<<<gProj, 256, SMEM_BYTES>>>(X, Wv, bv, v, MTOK, HID, HID, HID, HID, HID, 0, 0, 0, 1.f);

    repack_qk<<<dim3(4, 4, 2048), dim3(32, 8)>>>(q, qp);
    repack_qk<<<dim3(4, 4, 2048), dim3(32, 8)>>>(k, kp);
    repack_v <<<dim3(64, 2048), 256>>>(v, vpt);

    // scores = SCALE * Qp @ Kp^T
    gemm_tf32<<<dim3(2, 2, NT), 256, SMEM_BYTES>>>(qp, kp, nullptr, sc,
                                      P_, P_, D_, D_, D_, P_,
                                      (long)P_ * D_, (long)P_ * D_, (long)P_ * P_, SCALE);

    softmax_rows<<<NT * 256 / 8, 256>>>(sc);

    // ctx = probs @ Vp
    gemm_tf32<<<dim3(1, 2, NT), 256, SMEM_BYTES>>>(sc, vpt, nullptr, ct,
                                      P_, D_, P_, P_, P_, D_,
                                      (long)P_ * P_, (long)D_ * P_, (long)P_ * D_, 1.f);

    rearrange_ctx<<<dim3(128, NT), 256>>>(ct, ca);

    gemm_tf32<<<gProj, 256, SMEM_BYTES>>>(ca, Wo, bo, out, MTOK, HID, HID, HID, HID, HID, 0, 0, 0, 1.f);
}

// round 4
// speedup vs baseline: 5.4877x; 1.6819x over previous
#include <cuda_runtime.h>
#include <cuda_fp16.h>
#include <stdint.h>

#define HID  2048
#define B_   4
#define S_   4096
#define P_   256
#define D_   128
#define NT   1024        // B*H*N attention tiles
#define MTOK 16384       // B*S rows
#define SCALE 0.08838834764831845f   // 1/sqrt(128)

// ---------------- scratch (static device globals) ---------------------------
__device__ __half g_xh [(long)MTOK*HID];       // X in fp16
__device__ __half g_wh [4][(long)HID*HID];     // Wq,Wk,Wv,Wo in fp16
__device__ __half g_qh [(long)MTOK*HID];       // Q projection (fp16)
__device__ __half g_kh [(long)MTOK*HID];
__device__ __half g_vh [(long)MTOK*HID];
__device__ __half g_qp [(long)NT*P_*D_];       // paged Q
__device__ __half g_kp [(long)NT*P_*D_];       // paged K
__device__ __half g_vpt[(long)NT*D_*P_];       // paged V^T
__device__ float  g_sc [(long)NT*P_*P_];       // scores (fp32)
__device__ __half g_ph [(long)NT*P_*P_];       // probs (fp16)
__device__ __half g_ct [(long)NT*P_*D_];       // ctx tiles (fp16)
__device__ __half g_ca [(long)MTOK*HID];       // ctx arranged (fp16)

// ---------------- FP16 tensor-core GEMM: C = alpha * A @ B^T (+bias) --------
// A: M x K fp16 row-major (lda), B: N x K fp16 row-major (ldb), batched z.
// BM=BN=128, BK=32 halves, 256 thr (8 warps 2x4), warp tile 64x32,
// mma.sync.m16n8k16.f16, cp.async double buffered, pad-40 rows.
#define PADH 40

template<bool OUT_HALF>
__global__ __launch_bounds__(256, 2)
void gemm_fp16(const __half* __restrict__ A, const __half* __restrict__ Bm,
               const float* __restrict__ bias, void* __restrict__ Cv,
               int K, int lda, int ldb, int ldc,
               long sA, long sB, long sC, float alpha)
{
    __shared__ __half As[2][128 * PADH];
    __shared__ __half Bs[2][128 * PADH];

    const int bz = blockIdx.z;
    A  += (long)bz * sA;
    Bm += (long)bz * sB;

    const int m0 = blockIdx.y * 128;
    const int n0 = blockIdx.x * 128;
    const int tid  = threadIdx.x;
    const int lane = tid & 31;
    const int wid  = tid >> 5;
    const int wm   = wid >> 2;          // 0..1 -> 64-row slab
    const int wn   = wid & 3;           // 0..3 -> 32-col slab
    const int g    = lane >> 2;         // 0..7
    const int tg   = lane & 3;          // 0..3

    float acc[4][4][4];
#pragma unroll
    for (int i = 0; i < 4; i++)
#pragma unroll
        for (int j = 0; j < 4; j++)
#pragma unroll
            for (int r = 0; r < 4; r++) acc[i][j][r] = 0.f;

    const int nK = K >> 5;

    auto prefetch = [&](int kt, int buf) {
#pragma unroll
        for (int u = 0; u < 2; u++) {
            int id   = tid + u * 256;       // 0..511
            int row  = id >> 2;             // 0..127
            int col8 = (id & 3) << 3;       // 0,8,16,24 (halves)
            const __half* ga = A  + (long)(m0 + row) * lda + kt * 32 + col8;
            const __half* gb = Bm + (long)(n0 + row) * ldb + kt * 32 + col8;
            uint32_t da = (uint32_t)__cvta_generic_to_shared(&As[buf][row * PADH + col8]);
            uint32_t db = (uint32_t)__cvta_generic_to_shared(&Bs[buf][row * PADH + col8]);
            asm volatile("cp.async.cg.shared.global [%0], [%1], 16;" :: "r"(da), "l"(ga));
            asm volatile("cp.async.cg.shared.global [%0], [%1], 16;" :: "r"(db), "l"(gb));
        }
        asm volatile("cp.async.commit_group;");
    };

    prefetch(0, 0);

    for (int t = 0; t < nK; t++) {
        if (t + 1 < nK) {
            prefetch(t + 1, (t + 1) & 1);
            asm volatile("cp.async.wait_group 1;");
        } else {
            asm volatile("cp.async.wait_group 0;");
        }
        __syncthreads();

        const __half* Ab = As[t & 1];
        const __half* Bb = Bs[t & 1];

#pragma unroll
        for (int k0 = 0; k0 < 32; k0 += 16) {
            uint32_t af[4][4], bf[4][2];
#pragma unroll
            for (int mi = 0; mi < 4; mi++) {
                int r0 = (wm * 64 + mi * 16 + g) * PADH + k0 + tg * 2;
                af[mi][0] = *(const uint32_t*)&Ab[r0];
                af[mi][1] = *(const uint32_t*)&Ab[r0 + 8 * PADH];
                af[mi][2] = *(const uint32_t*)&Ab[r0 + 8];
                af[mi][3] = *(const uint32_t*)&Ab[r0 + 8 * PADH + 8];
            }
#pragma unroll
            for (int ni = 0; ni < 4; ni++) {
                int c0 = (wn * 32 + ni * 8 + g) * PADH + k0 + tg * 2;
                bf[ni][0] = *(const uint32_t*)&Bb[c0];
                bf[ni][1] = *(const uint32_t*)&Bb[c0 + 8];
            }
#pragma unroll
            for (int mi = 0; mi < 4; mi++)
#pragma unroll
                for (int ni = 0; ni < 4; ni++) {
                    asm volatile(
                        "mma.sync.aligned.m16n8k16.row.col.f32.f16.f16.f32 "
                        "{%0,%1,%2,%3}, {%4,%5,%6,%7}, {%8,%9}, {%0,%1,%2,%3};"
                        : "+f"(acc[mi][ni][0]), "+f"(acc[mi][ni][1]),
                          "+f"(acc[mi][ni][2]), "+f"(acc[mi][ni][3])
                        : "r"(af[mi][0]), "r"(af[mi][1]),
                          "r"(af[mi][2]), "r"(af[mi][3]),
                          "r"(bf[ni][0]), "r"(bf[ni][1]));
                }
        }
        __syncthreads();
    }

    // epilogue
#pragma unroll
    for (int mi = 0; mi < 4; mi++) {
#pragma unroll
        for (int ni = 0; ni < 4; ni++) {
            int row = m0 + wm * 64 + mi * 16 + g;
            int col = n0 + wn * 32 + ni * 8 + 2 * tg;
            float b0 = 0.f, b1 = 0.f;
            if (bias) { b0 = bias[col]; b1 = bias[col + 1]; }
            float v00 = alpha * acc[mi][ni][0] + b0;
            float v01 = alpha * acc[mi][ni][1] + b1;
            float v10 = alpha * acc[mi][ni][2] + b0;
            float v11 = alpha * acc[mi][ni][3] + b1;
            if (OUT_HALF) {
                __half* C = (__half*)Cv + (long)bz * sC;
                *(__half2*)(C + (long)row * ldc + col) =
                    __floats2half2_rn(v00, v01);
                *(__half2*)(C + (long)(row + 8) * ldc + col) =
                    __floats2half2_rn(v10, v11);
            } else {
                float* C = (float*)Cv + (long)bz * sC;
                *(float2*)(C + (long)row * ldc + col)       = make_float2(v00, v01);
                *(float2*)(C + (long)(row + 8) * ldc + col) = make_float2(v10, v11);
            }
        }
    }
}

// ---------------- f32 -> f16 conversion -------------------------------------
__global__ void conv_f16(const float* __restrict__ in, __half* __restrict__ out, int n4)
{
    int i = blockIdx.x * 256 + threadIdx.x;
    if (i < n4) {
        float4 v = ((const float4*)in)[i];
        __half2 lo = __floats2half2_rn(v.x, v.y);
        __half2 hi = __floats2half2_rn(v.z, v.w);
        ((__half2*)out)[2 * i]     = lo;
        ((__half2*)out)[2 * i + 1] = hi;
    }
}

// ---------------- repack Q/K into paged layout (fp16) -----------------------
// paged[t][p2=2d+j][d2=r] = heads[b,h, n*256 + j*128 + r, d]
__global__ void repack_qk(const __half* __restrict__ in, __half* __restrict__ out)
{
    __shared__ __half tile[32][34];
    const int bz = blockIdx.z;
    const int j = bz & 1, n = (bz >> 1) & 15, h = (bz >> 5) & 15, b = bz >> 9;
    const __half* ib = in + ((long)(b * S_ + n * 256 + j * 128)) * HID + h * 128;
    __half* ob = out + (long)((b * 16 + h) * 16 + n) * (P_ * D_);
    const int d0 = blockIdx.x * 32, r0 = blockIdx.y * 32;
    const int tx = threadIdx.x, ty = threadIdx.y;
#pragma unroll
    for (int i = 0; i < 32; i += 8)
        tile[ty + i][tx] = ib[(long)(r0 + ty + i) * HID + d0 + tx];
    __syncthreads();
#pragma unroll
    for (int i = 0; i < 32; i += 8)
        ob[(long)(2 * (d0 + ty + i) + j) * D_ + r0 + tx] = tile[tx][ty + i];
}

// ---------------- repack V transposed: vpt[t][d2=r][k2=2d+j] -----------------
__global__ void repack_v(const __half* __restrict__ in, __half* __restrict__ out)
{
    const int bz = blockIdx.y;
    const int j = bz & 1, n = (bz >> 1) & 15, h = (bz >> 5) & 15, b = bz >> 9;
    const int idx = blockIdx.x * 256 + threadIdx.x;
    const int r = idx >> 7, d = idx & 127;
    const __half* ib = in + ((long)(b * S_ + n * 256 + j * 128)) * HID + h * 128;
    long t = (b * 16 + h) * 16 + n;
    out[t * (long)(D_ * P_) + (long)r * P_ + 2 * d + j] = ib[(long)r * HID + d];
}

// ---------------- softmax over rows of 256: fp32 in, fp16 out ---------------
__global__ void softmax_rows(const float* __restrict__ Smat, __half* __restrict__ Pm)
{
    const int warp = (blockIdx.x * blockDim.x + threadIdx.x) >> 5;
    const int lane = threadIdx.x & 31;
    const float* row = Smat + (long)warp * 256;
    __half* orow = Pm + (long)warp * 256;
    float v[8];
    float mx = -1e30f;
#pragma unroll
    for (int i = 0; i < 8; i++) { v[i] = row[lane + i * 32]; mx = fmaxf(mx, v[i]); }
#pragma unroll
    for (int o = 16; o; o >>= 1) mx = fmaxf(mx, __shfl_xor_sync(~0u, mx, o));
    float s = 0.f;
#pragma unroll
    for (int i = 0; i < 8; i++) { v[i] = __expf(v[i] - mx); s += v[i]; }
#pragma unroll
    for (int o = 16; o; o >>= 1) s += __shfl_xor_sync(~0u, s, o);
    const float inv = 1.f / s;
#pragma unroll
    for (int i = 0; i < 8; i++) orow[lane + i * 32] = __float2half(v[i] * inv);
}

// ---------------- ctx tiles -> (B,S,HID) arrangement (fp16) -----------------
__global__ void rearrange_ctx(const __half* __restrict__ in, __half* __restrict__ out)
{
    const long t = blockIdx.y;
    const int b = (int)(t >> 8), h = (int)((t >> 4) & 15), n = (int)(t & 15);
    const int idx = blockIdx.x * 256 + threadIdx.x;
    const int p2 = idx >> 7, d2 = idx & 127;
    out[((long)(b * 4096 + h * 256 + p2)) * HID + n * 128 + d2] = in[t * 32768 + idx];
}

// ---------------- launch -----------------------------------------------------
extern "C" void kernel_launch(void* const* d_in, const int* in_sizes, int n_in,
                              void* d_out, int out_size)
{
    const float* X  = (const float*)d_in[0];
    const float* Wq = (const float*)d_in[1];
    const float* bq = (const float*)d_in[2];
    const float* Wk = (const float*)d_in[3];
    const float* bk = (const float*)d_in[4];
    const float* Wv = (const float*)d_in[5];
    const float* bv = (const float*)d_in[6];
    const float* Wo = (const float*)d_in[7];
    const float* bo = (const float*)d_in[8];
    float* out = (float*)d_out;

    __half *xh, *wh, *qh, *kh, *vh, *qp, *kp, *vpt, *ph, *ct, *ca;
    float *sc;
    cudaGetSymbolAddress((void**)&xh,  g_xh);
    cudaGetSymbolAddress((void**)&wh,  g_wh);
    cudaGetSymbolAddress((void**)&qh,  g_qh);
    cudaGetSymbolAddress((void**)&kh,  g_kh);
    cudaGetSymbolAddress((void**)&vh,  g_vh);
    cudaGetSymbolAddress((void**)&qp,  g_qp);
    cudaGetSymbolAddress((void**)&kp,  g_kp);
    cudaGetSymbolAddress((void**)&vpt, g_vpt);
    cudaGetSymbolAddress((void**)&sc,  g_sc);
    cudaGetSymbolAddress((void**)&ph,  g_ph);
    cudaGetSymbolAddress((void**)&ct,  g_ct);
    cudaGetSymbolAddress((void**)&ca,  g_ca);

    const long WSZ = (long)HID * HID;

    // convert GEMM operands to fp16
    conv_f16<<<(MTOK * HID / 4 + 255) / 256, 256>>>(X, xh, MTOK * HID / 4);
    conv_f16<<<(int)(WSZ / 4 + 255) / 256, 256>>>(Wq, wh + 0 * WSZ, (int)(WSZ / 4));
    conv_f16<<<(int)(WSZ / 4 + 255) / 256, 256>>>(Wk, wh + 1 * WSZ, (int)(WSZ / 4));
    conv_f16<<<(int)(WSZ / 4 + 255) / 256, 256>>>(Wv, wh + 2 * WSZ, (int)(WSZ / 4));
    conv_f16<<<(int)(WSZ / 4 + 255) / 256, 256>>>(Wo, wh + 3 * WSZ, (int)(WSZ / 4));

    // QKV projections (fp16 out)
    dim3 gProj(HID / 128, MTOK / 128, 1);   // 16 x 128
    gemm_fp16<true><<<gProj, 256>>>(xh, wh + 0 * WSZ, bq, qh,
                                    HID, HID, HID, HID, 0, 0, 0, 1.f);
    gemm_fp16<true><<<gProj, 256>>>(xh, wh + 1 * WSZ, bk, kh,
                                    HID, HID, HID, HID, 0, 0, 0, 1.f);
    gemm_fp16<true><<<gProj, 256>>>(xh, wh + 2 * WSZ, bv, vh,
                                    HID, HID, HID, HID, 0, 0, 0, 1.f);

    // repack into paged layout
    repack_qk<<<dim3(4, 4, 2048), dim3(32, 8)>>>(qh, qp);
    repack_qk<<<dim3(4, 4, 2048), dim3(32, 8)>>>(kh, kp);
    repack_v <<<dim3(64, 2048), 256>>>(vh, vpt);

    // scores = SCALE * Qp @ Kp^T (fp32 out)
    gemm_fp16<false><<<dim3(2, 2, NT), 256>>>(qp, kp, nullptr, sc,
                                              D_, D_, D_, P_,
                                              (long)P_ * D_, (long)P_ * D_, (long)P_ * P_,
                                              SCALE);

    // softmax -> fp16 probs
    softmax_rows<<<NT * 256 / 8, 256>>>(sc, ph);

    // ctx = probs @ Vp (fp16 out)
    gemm_fp16<true><<<dim3(1, 2, NT), 256>>>(ph, vpt, nullptr, ct,
                                             P_, P_, P_, D_,
                                             (long)P_ * P_, (long)D_ * P_, (long)P_ * D_,
                                             1.f);

    rearrange_ctx<<<dim3(128, NT), 256>>>(ct, ca);

    // output projection (fp32 out + bias)
    gemm_fp16<false><<<gProj, 256>>>(ca, wh + 3 * WSZ, bo, out,
                                     HID, HID, HID, HID, 0, 0, 0, 1.f);
}

// round 5
// speedup vs baseline: 6.1443x; 1.1197x over previous
#include <cuda_runtime.h>
#include <cuda_fp16.h>
#include <stdint.h>

#define HID  2048
#define B_   4
#define S_   4096
#define P_   256
#define D_   128
#define NT   1024        // B*H*N attention tiles
#define MTOK 16384       // B*S rows
#define SCALE 0.08838834764831845f   // 1/sqrt(128)

// ---------------- scratch (static device globals) ---------------------------
__device__ __half g_xh [(long)MTOK*HID];       // X in fp16
__device__ __half g_wh [4][(long)HID*HID];     // Wq,Wk,Wv,Wo in fp16
__device__ __half g_qh [(long)MTOK*HID];
__device__ __half g_kh [(long)MTOK*HID];
__device__ __half g_vh [(long)MTOK*HID];
__device__ __half g_qp [(long)NT*P_*D_];       // paged Q
__device__ __half g_kp [(long)NT*P_*D_];       // paged K
__device__ __half g_vpt[(long)NT*D_*P_];       // paged V^T
__device__ float  g_sc [(long)NT*P_*P_];       // scores (fp32)
__device__ __half g_ph [(long)NT*P_*P_];       // probs (fp16)
__device__ __half g_ca [(long)MTOK*HID];       // ctx arranged (fp16)

// ---------------- FP16 tensor-core GEMM: C = alpha * A @ B^T (+bias) --------
// BM=BN=128, BK=32 halves, 256 thr (8 warps 2x4), warp tile 64x32,
// mma.sync.m16n8k16.f32.f16, ldmatrix.x4 fragments, cp.async double buffer.
// CTX mode: C base computed from blockIdx.z (fused rearrange for PV GEMM).
#define PADH 40
#define BUFH (128 * PADH)

template<bool OUT_HALF, bool CTX>
__global__ __launch_bounds__(256, 2)
void gemm_fp16(const __half* __restrict__ A, const __half* __restrict__ Bm,
               const float* __restrict__ bias, void* __restrict__ Cv,
               int K, int lda, int ldb, int ldc,
               long sA, long sB, long sC, float alpha)
{
    __shared__ __half As[2 * BUFH];
    __shared__ __half Bs[2 * BUFH];

    const int bz = blockIdx.z;
    A  += (long)bz * sA;
    Bm += (long)bz * sB;

    const int m0 = blockIdx.y * 128;
    const int n0 = blockIdx.x * 128;
    const int tid  = threadIdx.x;
    const int lane = tid & 31;
    const int wid  = tid >> 5;
    const int wm   = wid >> 2;          // 0..1 -> 64-row slab
    const int wn   = wid & 3;           // 0..3 -> 32-col slab
    const int g    = lane >> 2;         // 0..7
    const int tg   = lane & 3;          // 0..3

    float acc[4][4][4];
#pragma unroll
    for (int i = 0; i < 4; i++)
#pragma unroll
        for (int j = 0; j < 4; j++)
#pragma unroll
            for (int r = 0; r < 4; r++) acc[i][j][r] = 0.f;

    const int nK = K >> 5;

    // ldmatrix lane->address bases (halves)
    const uint32_t sA0 = (uint32_t)__cvta_generic_to_shared(As);
    const uint32_t sB0 = (uint32_t)__cvta_generic_to_shared(Bs);
    // A: lanes 0-15 -> rows 0-15 @k0 ; lanes 16-31 -> rows 0-15 @k0+8
    const uint32_t aBase = sA0 + (((wm * 64 + (lane & 15)) * PADH) + (lane >> 4) * 8) * 2;
    // B: lanes 0-7 rows+0 k0 ; 8-15 rows+0 k8 ; 16-23 rows+8 k0 ; 24-31 rows+8 k8
    const uint32_t bBase = sB0 + (((wn * 32 + (lane & 7) + ((lane >> 4) << 3)) * PADH)
                                  + ((lane >> 3) & 1) * 8) * 2;

    auto prefetch = [&](int kt, int buf) {
#pragma unroll
        for (int u = 0; u < 2; u++) {
            int id   = tid + u * 256;       // 0..511
            int row  = id >> 2;             // 0..127
            int col8 = (id & 3) << 3;       // 0,8,16,24 halves
            const __half* ga = A  + (long)(m0 + row) * lda + kt * 32 + col8;
            const __half* gb = Bm + (long)(n0 + row) * ldb + kt * 32 + col8;
            uint32_t da = (uint32_t)__cvta_generic_to_shared(&As[buf * BUFH + row * PADH + col8]);
            uint32_t db = (uint32_t)__cvta_generic_to_shared(&Bs[buf * BUFH + row * PADH + col8]);
            asm volatile("cp.async.cg.shared.global [%0], [%1], 16;" :: "r"(da), "l"(ga));
            asm volatile("cp.async.cg.shared.global [%0], [%1], 16;" :: "r"(db), "l"(gb));
        }
        asm volatile("cp.async.commit_group;");
    };

    prefetch(0, 0);

    for (int t = 0; t < nK; t++) {
        if (t + 1 < nK) {
            prefetch(t + 1, (t + 1) & 1);
            asm volatile("cp.async.wait_group 1;");
        } else {
            asm volatile("cp.async.wait_group 0;");
        }
        __syncthreads();

        const uint32_t bufOff = (uint32_t)((t & 1) * BUFH * 2);

#pragma unroll
        for (int k0 = 0; k0 < 32; k0 += 16) {
            uint32_t af[4][4], bf[4][2];
            const uint32_t ak = aBase + bufOff + k0 * 2;
            const uint32_t bk = bBase + bufOff + k0 * 2;
#pragma unroll
            for (int mi = 0; mi < 4; mi++) {
                asm volatile(
                    "ldmatrix.sync.aligned.m8n8.x4.shared.b16 {%0,%1,%2,%3}, [%4];"
                    : "=r"(af[mi][0]), "=r"(af[mi][1]),
                      "=r"(af[mi][2]), "=r"(af[mi][3])
                    : "r"(ak + (uint32_t)(mi * 16 * PADH * 2)));
            }
#pragma unroll
            for (int p = 0; p < 2; p++) {
                asm volatile(
                    "ldmatrix.sync.aligned.m8n8.x4.shared.b16 {%0,%1,%2,%3}, [%4];"
                    : "=r"(bf[2*p][0]), "=r"(bf[2*p][1]),
                      "=r"(bf[2*p+1][0]), "=r"(bf[2*p+1][1])
                    : "r"(bk + (uint32_t)(p * 16 * PADH * 2)));
            }
#pragma unroll
            for (int mi = 0; mi < 4; mi++)
#pragma unroll
                for (int ni = 0; ni < 4; ni++) {
                    asm volatile(
                        "mma.sync.aligned.m16n8k16.row.col.f32.f16.f16.f32 "
                        "{%0,%1,%2,%3}, {%4,%5,%6,%7}, {%8,%9}, {%0,%1,%2,%3};"
                        : "+f"(acc[mi][ni][0]), "+f"(acc[mi][ni][1]),
                          "+f"(acc[mi][ni][2]), "+f"(acc[mi][ni][3])
                        : "r"(af[mi][0]), "r"(af[mi][1]),
                          "r"(af[mi][2]), "r"(af[mi][3]),
                          "r"(bf[ni][0]), "r"(bf[ni][1]));
                }
        }
        __syncthreads();
    }

    // C base offset
    long cOff;
    if (CTX) {
        const int b = bz >> 8, h = (bz >> 4) & 15, n = bz & 15;
        cOff = ((long)(b * 4096 + h * 256)) * HID + n * 128;
    } else {
        cOff = (long)bz * sC;
    }

    // epilogue
#pragma unroll
    for (int mi = 0; mi < 4; mi++) {
#pragma unroll
        for (int ni = 0; ni < 4; ni++) {
            int row = m0 + wm * 64 + mi * 16 + g;
            int col = n0 + wn * 32 + ni * 8 + 2 * tg;
            float b0 = 0.f, b1 = 0.f;
            if (bias) { b0 = bias[col]; b1 = bias[col + 1]; }
            float v00 = alpha * acc[mi][ni][0] + b0;
            float v01 = alpha * acc[mi][ni][1] + b1;
            float v10 = alpha * acc[mi][ni][2] + b0;
            float v11 = alpha * acc[mi][ni][3] + b1;
            if (OUT_HALF) {
                __half* C = (__half*)Cv + cOff;
                *(__half2*)(C + (long)row * ldc + col)       = __floats2half2_rn(v00, v01);
                *(__half2*)(C + (long)(row + 8) * ldc + col) = __floats2half2_rn(v10, v11);
            } else {
                float* C = (float*)Cv + cOff;
                *(float2*)(C + (long)row * ldc + col)       = make_float2(v00, v01);
                *(float2*)(C + (long)(row + 8) * ldc + col) = make_float2(v10, v11);
            }
        }
    }
}

// ---------------- f32 -> f16 conversion -------------------------------------
__global__ void conv_f16(const float* __restrict__ in, __half* __restrict__ out, int n4)
{
    int i = blockIdx.x * 256 + threadIdx.x;
    if (i < n4) {
        float4 v = ((const float4*)in)[i];
        ((__half2*)out)[2 * i]     = __floats2half2_rn(v.x, v.y);
        ((__half2*)out)[2 * i + 1] = __floats2half2_rn(v.z, v.w);
    }
}

// ---------------- repack Q/K into paged layout (fp16) -----------------------
__global__ void repack_qk(const __half* __restrict__ in, __half* __restrict__ out)
{
    __shared__ __half tile[32][34];
    const int bz = blockIdx.z;
    const int j = bz & 1, n = (bz >> 1) & 15, h = (bz >> 5) & 15, b = bz >> 9;
    const __half* ib = in + ((long)(b * S_ + n * 256 + j * 128)) * HID + h * 128;
    __half* ob = out + (long)((b * 16 + h) * 16 + n) * (P_ * D_);
    const int d0 = blockIdx.x * 32, r0 = blockIdx.y * 32;
    const int tx = threadIdx.x, ty = threadIdx.y;
#pragma unroll
    for (int i = 0; i < 32; i += 8)
        tile[ty + i][tx] = ib[(long)(r0 + ty + i) * HID + d0 + tx];
    __syncthreads();
#pragma unroll
    for (int i = 0; i < 32; i += 8)
        ob[(long)(2 * (d0 + ty + i) + j) * D_ + r0 + tx] = tile[tx][ty + i];
}

// ---------------- repack V transposed: vpt[t][d2=r][k2=2d+j] -----------------
__global__ void repack_v(const __half* __restrict__ in, __half* __restrict__ out)
{
    const int bz = blockIdx.y;
    const int j = bz & 1, n = (bz >> 1) & 15, h = (bz >> 5) & 15, b = bz >> 9;
    const int idx = blockIdx.x * 256 + threadIdx.x;
    const int r = idx >> 7, d = idx & 127;
    const __half* ib = in + ((long)(b * S_ + n * 256 + j * 128)) * HID + h * 128;
    long t = (b * 16 + h) * 16 + n;
    out[t * (long)(D_ * P_) + (long)r * P_ + 2 * d + j] = ib[(long)r * HID + d];
}

// ---------------- softmax over rows of 256: fp32 in, fp16 out ---------------
__global__ void softmax_rows(const float* __restrict__ Smat, __half* __restrict__ Pm)
{
    const int warp = (blockIdx.x * blockDim.x + threadIdx.x) >> 5;
    const int lane = threadIdx.x & 31;
    const float* row = Smat + (long)warp * 256;
    __half* orow = Pm + (long)warp * 256;
    float v[8];
    float mx = -1e30f;
#pragma unroll
    for (int i = 0; i < 8; i++) { v[i] = row[lane + i * 32]; mx = fmaxf(mx, v[i]); }
#pragma unroll
    for (int o = 16; o; o >>= 1) mx = fmaxf(mx, __shfl_xor_sync(~0u, mx, o));
    float s = 0.f;
#pragma unroll
    for (int i = 0; i < 8; i++) { v[i] = __expf(v[i] - mx); s += v[i]; }
#pragma unroll
    for (int o = 16; o; o >>= 1) s += __shfl_xor_sync(~0u, s, o);
    const float inv = 1.f / s;
#pragma unroll
    for (int i = 0; i < 8; i++) orow[lane + i * 32] = __float2half(v[i] * inv);
}

// ---------------- launch -----------------------------------------------------
extern "C" void kernel_launch(void* const* d_in, const int* in_sizes, int n_in,
                              void* d_out, int out_size)
{
    const float* X  = (const float*)d_in[0];
    const float* Wq = (const float*)d_in[1];
    const float* bq = (const float*)d_in[2];
    const float* Wk = (const float*)d_in[3];
    const float* bk = (const float*)d_in[4];
    const float* Wv = (const float*)d_in[5];
    const float* bv = (const float*)d_in[6];
    const float* Wo = (const float*)d_in[7];
    const float* bo = (const float*)d_in[8];
    float* out = (float*)d_out;

    __half *xh, *wh, *qh, *kh, *vh, *qp, *kp, *vpt, *ph, *ca;
    float *sc;
    cudaGetSymbolAddress((void**)&xh,  g_xh);
    cudaGetSymbolAddress((void**)&wh,  g_wh);
    cudaGetSymbolAddress((void**)&qh,  g_qh);
    cudaGetSymbolAddress((void**)&kh,  g_kh);
    cudaGetSymbolAddress((void**)&vh,  g_vh);
    cudaGetSymbolAddress((void**)&qp,  g_qp);
    cudaGetSymbolAddress((void**)&kp,  g_kp);
    cudaGetSymbolAddress((void**)&vpt, g_vpt);
    cudaGetSymbolAddress((void**)&sc,  g_sc);
    cudaGetSymbolAddress((void**)&ph,  g_ph);
    cudaGetSymbolAddress((void**)&ca,  g_ca);

    const long WSZ = (long)HID * HID;

    conv_f16<<<(MTOK * HID / 4 + 255) / 256, 256>>>(X, xh, MTOK * HID / 4);
    conv_f16<<<(int)(WSZ / 4 + 255) / 256, 256>>>(Wq, wh + 0 * WSZ, (int)(WSZ / 4));
    conv_f16<<<(int)(WSZ / 4 + 255) / 256, 256>>>(Wk, wh + 1 * WSZ, (int)(WSZ / 4));
    conv_f16<<<(int)(WSZ / 4 + 255) / 256, 256>>>(Wv, wh + 2 * WSZ, (int)(WSZ / 4));
    conv_f16<<<(int)(WSZ / 4 + 255) / 256, 256>>>(Wo, wh + 3 * WSZ, (int)(WSZ / 4));

    dim3 gProj(HID / 128, MTOK / 128, 1);   // 16 x 128
    gemm_fp16<true,  false><<<gProj, 256>>>(xh, wh + 0 * WSZ, bq, qh,
                                            HID, HID, HID, HID, 0, 0, 0, 1.f);
    gemm_fp16<true,  false><<<gProj, 256>>>(xh, wh + 1 * WSZ, bk, kh,
                                            HID, HID, HID, HID, 0, 0, 0, 1.f);
    gemm_fp16<true,  false><<<gProj, 256>>>(xh, wh + 2 * WSZ, bv, vh,
                                            HID, HID, HID, HID, 0, 0, 0, 1.f);

    repack_qk<<<dim3(4, 4, 2048), dim3(32, 8)>>>(qh, qp);
    repack_qk<<<dim3(4, 4, 2048), dim3(32, 8)>>>(kh, kp);
    repack_v <<<dim3(64, 2048), 256>>>(vh, vpt);

    // scores = SCALE * Qp @ Kp^T (fp32 out)
    gemm_fp16<false, false><<<dim3(2, 2, NT), 256>>>(qp, kp, nullptr, sc,
                                                     D_, D_, D_, P_,
                                                     (long)P_ * D_, (long)P_ * D_,
                                                     (long)P_ * P_, SCALE);

    softmax_rows<<<NT * 256 / 8, 256>>>(sc, ph);

    // ctx = probs @ Vp, fused rearrange into epilogue (writes g_ca directly)
    gemm_fp16<true,  true><<<dim3(1, 2, NT), 256>>>(ph, vpt, nullptr, ca,
                                                    P_, P_, P_, HID,
                                                    (long)P_ * P_, (long)D_ * P_, 0, 1.f);

    // output projection (fp32 out + bias)
    gemm_fp16<false, false><<<gProj, 256>>>(ca, wh + 3 * WSZ, bo, out,
                                            HID, HID, HID, HID, 0, 0, 0, 1.f);
}

// round 6
// speedup vs baseline: 6.5929x; 1.0730x over previous
#include <cuda_runtime.h>
#include <cuda_fp16.h>
#include <stdint.h>

#define HID  2048
#define B_   4
#define S_   4096
#define P_   256
#define D_   128
#define NT   1024
#define MTOK 16384
#define SCALE 0.08838834764831845f

// ---------------- scratch ----------------------------------------------------
__device__ __half g_xh [(long)MTOK*HID];
__device__ __half g_wh [4][(long)HID*HID];
__device__ float  g_bias[3*HID];
__device__ __half g_qkv[3][(long)MTOK*HID];
__device__ __half g_qp [(long)NT*P_*D_];
__device__ __half g_kp [(long)NT*P_*D_];
__device__ __half g_vpt[(long)NT*D_*P_];
__device__ __half g_ca [(long)MTOK*HID];

__device__ __forceinline__ void cpa16(uint32_t d, const void* g) {
    asm volatile("cp.async.cg.shared.global [%0], [%1], 16;" :: "r"(d), "l"(g));
}
__device__ __forceinline__ uint32_t packh2(float a, float b) {
    __half2 h = __floats2half2_rn(a, b);
    return *(uint32_t*)&h;
}

#define LDSM4(r0,r1,r2,r3, addr) \
    asm volatile("ldmatrix.sync.aligned.m8n8.x4.shared.b16 {%0,%1,%2,%3}, [%4];" \
        : "=r"(r0), "=r"(r1), "=r"(r2), "=r"(r3) : "r"(addr))

#define MMA(d, a0,a1,a2,a3, b0,b1) \
    asm volatile("mma.sync.aligned.m16n8k16.row.col.f32.f16.f16.f32 " \
        "{%0,%1,%2,%3}, {%4,%5,%6,%7}, {%8,%9}, {%0,%1,%2,%3};" \
        : "+f"((d)[0]), "+f"((d)[1]), "+f"((d)[2]), "+f"((d)[3]) \
        : "r"(a0), "r"(a1), "r"(a2), "r"(a3), "r"(b0), "r"(b1))

// ---------------- FP16 GEMM: C = alpha * A @ B^T (+bias), batched ------------
#define PADH 40
#define BUFH (128 * PADH)

template<bool OUT_HALF>
__global__ __launch_bounds__(256, 2)
void gemm_fp16(const __half* __restrict__ A, const __half* __restrict__ Bm,
               const float* __restrict__ bias, void* __restrict__ Cv,
               int K, int lda, int ldb, int ldc,
               long sA, long sB, long sBias, long sC, float alpha)
{
    __shared__ __half As[2 * BUFH];
    __shared__ __half Bs[2 * BUFH];

    const int bz = blockIdx.z;
    A  += (long)bz * sA;
    Bm += (long)bz * sB;
    if (bias) bias += (long)bz * sBias;

    const int m0 = blockIdx.y * 128;
    const int n0 = blockIdx.x * 128;
    const int tid  = threadIdx.x;
    const int lane = tid & 31;
    const int wid  = tid >> 5;
    const int wm   = wid >> 2;
    const int wn   = wid & 3;
    const int g    = lane >> 2;
    const int tg   = lane & 3;

    float acc[4][4][4];
#pragma unroll
    for (int i = 0; i < 4; i++)
#pragma unroll
        for (int j = 0; j < 4; j++)
#pragma unroll
            for (int r = 0; r < 4; r++) acc[i][j][r] = 0.f;

    const int nK = K >> 5;

    const uint32_t sA0 = (uint32_t)__cvta_generic_to_shared(As);
    const uint32_t sB0 = (uint32_t)__cvta_generic_to_shared(Bs);
    const uint32_t aBase = sA0 + (((wm * 64 + (lane & 15)) * PADH) + (lane >> 4) * 8) * 2;
    const uint32_t bBase = sB0 + (((wn * 32 + (lane & 7) + ((lane >> 4) << 3)) * PADH)
                                  + ((lane >> 3) & 1) * 8) * 2;

    auto prefetch = [&](int kt, int buf) {
#pragma unroll
        for (int u = 0; u < 2; u++) {
            int id   = tid + u * 256;
            int row  = id >> 2;
            int col8 = (id & 3) << 3;
            const __half* ga = A  + (long)(m0 + row) * lda + kt * 32 + col8;
            const __half* gb = Bm + (long)(n0 + row) * ldb + kt * 32 + col8;
            cpa16((uint32_t)__cvta_generic_to_shared(&As[buf * BUFH + row * PADH + col8]), ga);
            cpa16((uint32_t)__cvta_generic_to_shared(&Bs[buf * BUFH + row * PADH + col8]), gb);
        }
        asm volatile("cp.async.commit_group;");
    };

    prefetch(0, 0);

    for (int t = 0; t < nK; t++) {
        if (t + 1 < nK) {
            prefetch(t + 1, (t + 1) & 1);
            asm volatile("cp.async.wait_group 1;");
        } else {
            asm volatile("cp.async.wait_group 0;");
        }
        __syncthreads();

        const uint32_t bufOff = (uint32_t)((t & 1) * BUFH * 2);

#pragma unroll
        for (int k0 = 0; k0 < 32; k0 += 16) {
            uint32_t af[4][4], bf[4][2];
            const uint32_t ak = aBase + bufOff + k0 * 2;
            const uint32_t bk = bBase + bufOff + k0 * 2;
#pragma unroll
            for (int mi = 0; mi < 4; mi++)
                LDSM4(af[mi][0], af[mi][1], af[mi][2], af[mi][3],
                      ak + (uint32_t)(mi * 16 * PADH * 2));
#pragma unroll
            for (int p = 0; p < 2; p++)
                LDSM4(bf[2*p][0], bf[2*p][1], bf[2*p+1][0], bf[2*p+1][1],
                      bk + (uint32_t)(p * 16 * PADH * 2));
#pragma unroll
            for (int mi = 0; mi < 4; mi++)
#pragma unroll
                for (int ni = 0; ni < 4; ni++)
                    MMA(acc[mi][ni], af[mi][0], af[mi][1], af[mi][2], af[mi][3],
                        bf[ni][0], bf[ni][1]);
        }
        __syncthreads();
    }

    const long cOff = (long)bz * sC;
#pragma unroll
    for (int mi = 0; mi < 4; mi++) {
#pragma unroll
        for (int ni = 0; ni < 4; ni++) {
            int row = m0 + wm * 64 + mi * 16 + g;
            int col = n0 + wn * 32 + ni * 8 + 2 * tg;
            float b0 = 0.f, b1 = 0.f;
            if (bias) { b0 = bias[col]; b1 = bias[col + 1]; }
            float v00 = alpha * acc[mi][ni][0] + b0;
            float v01 = alpha * acc[mi][ni][1] + b1;
            float v10 = alpha * acc[mi][ni][2] + b0;
            float v11 = alpha * acc[mi][ni][3] + b1;
            if (OUT_HALF) {
                __half* C = (__half*)Cv + cOff;
                *(__half2*)(C + (long)row * ldc + col)       = __floats2half2_rn(v00, v01);
                *(__half2*)(C + (long)(row + 8) * ldc + col) = __floats2half2_rn(v10, v11);
            } else {
                float* C = (float*)Cv + cOff;
                *(float2*)(C + (long)row * ldc + col)       = make_float2(v00, v01);
                *(float2*)(C + (long)(row + 8) * ldc + col) = make_float2(v10, v11);
            }
        }
    }
}

// ---------------- fused attention: S = Q@K^T, softmax, ctx = P@V -------------
// grid (2, NT): x = 128-row half, y = tile t. 256 thr, 8 warps x 16 rows.
#define PADQ 136
#define PADK 136
#define PADV 264
#define ATT_SMEM ((128*PADQ + 256*PADK + 128*PADV) * 2)   // 172032

__global__ __launch_bounds__(256, 1)
void attn_fused(const __half* __restrict__ qp, const __half* __restrict__ kp,
                const __half* __restrict__ vpt, __half* __restrict__ ca)
{
    extern __shared__ __half sm[];
    const int t = blockIdx.y, mh = blockIdx.x;
    const int tid = threadIdx.x, lane = tid & 31, w = tid >> 5;

    const __half* qg = qp  + (long)t * 32768 + mh * 16384;
    const __half* kg = kp  + (long)t * 32768;
    const __half* vg = vpt + (long)t * 32768;

    const uint32_t qsu = (uint32_t)__cvta_generic_to_shared(sm);
    const uint32_t ksu = qsu + 128 * PADQ * 2;
    const uint32_t vsu = ksu + 256 * PADK * 2;

    // G0: Q + K chunk 0
#pragma unroll
    for (int u = 0; u < 8; u++) {
        int id = tid + u * 256, row = id >> 4, seg = id & 15;
        cpa16(qsu + (row * PADQ + seg * 8) * 2, qg + row * 128 + seg * 8);
    }
#pragma unroll
    for (int u = 0; u < 4; u++) {
        int id = tid + u * 256, row = id >> 4, seg = id & 15;
        cpa16(ksu + (row * PADK + seg * 8) * 2, kg + row * 128 + seg * 8);
    }
    asm volatile("cp.async.commit_group;");
    // G1..G3: K chunks 1..3
#pragma unroll
    for (int c = 1; c < 4; c++) {
#pragma unroll
        for (int u = 0; u < 4; u++) {
            int id = tid + u * 256, row = (id >> 4) + c * 64, seg = id & 15;
            cpa16(ksu + (row * PADK + seg * 8) * 2, kg + row * 128 + seg * 8);
        }
        asm volatile("cp.async.commit_group;");
    }
    // G4: V (128 x 256)
#pragma unroll
    for (int u = 0; u < 16; u++) {
        int id = tid + u * 256, row = id >> 5, seg = id & 31;
        cpa16(vsu + (row * PADV + seg * 8) * 2, vg + row * 256 + seg * 8);
    }
    asm volatile("cp.async.commit_group;");

    const uint32_t aB   = qsu + ((w * 16 + (lane & 15)) * PADQ + (lane >> 4) * 8) * 2;
    const uint32_t rsel = (lane & 7) + ((lane >> 4) << 3);
    const uint32_t koff = ((lane >> 3) & 1) * 8;
    const uint32_t bBK  = ksu + (rsel * PADK + koff) * 2;
    const uint32_t bBV  = vsu + (rsel * PADV + koff) * 2;

    float acc[32][4];
#pragma unroll
    for (int i = 0; i < 32; i++)
        acc[i][0] = acc[i][1] = acc[i][2] = acc[i][3] = 0.f;

    asm volatile("cp.async.wait_group 4;");
    __syncthreads();

    uint32_t qa[8][4];
#pragma unroll
    for (int k8 = 0; k8 < 8; k8++)
        LDSM4(qa[k8][0], qa[k8][1], qa[k8][2], qa[k8][3], aB + k8 * 32);

    // S = Q @ K^T over 4 column-chunks of 64
#pragma unroll
    for (int c = 0; c < 4; c++) {
        if (c == 1) { asm volatile("cp.async.wait_group 3;"); __syncthreads(); }
        if (c == 2) { asm volatile("cp.async.wait_group 2;"); __syncthreads(); }
        if (c == 3) { asm volatile("cp.async.wait_group 1;"); __syncthreads(); }
#pragma unroll
        for (int k8 = 0; k8 < 8; k8++) {
#pragma unroll
            for (int p = 0; p < 4; p++) {
                uint32_t b0, b1, b2, b3;
                LDSM4(b0, b1, b2, b3,
                      bBK + (uint32_t)((c * 64 + p * 16) * PADK * 2) + k8 * 32);
                MMA(acc[c*8+p*2],   qa[k8][0], qa[k8][1], qa[k8][2], qa[k8][3], b0, b1);
                MMA(acc[c*8+p*2+1], qa[k8][0], qa[k8][1], qa[k8][2], qa[k8][3], b2, b3);
            }
        }
    }

    // softmax over 256 cols; rows g (regs 0,1) and g+8 (regs 2,3)
    float mx0 = -1e30f, mx1 = -1e30f;
#pragma unroll
    for (int i = 0; i < 32; i++) {
        mx0 = fmaxf(mx0, fmaxf(acc[i][0], acc[i][1]));
        mx1 = fmaxf(mx1, fmaxf(acc[i][2], acc[i][3]));
    }
    mx0 = fmaxf(mx0, __shfl_xor_sync(~0u, mx0, 1));
    mx0 = fmaxf(mx0, __shfl_xor_sync(~0u, mx0, 2));
    mx1 = fmaxf(mx1, __shfl_xor_sync(~0u, mx1, 1));
    mx1 = fmaxf(mx1, __shfl_xor_sync(~0u, mx1, 2));
    float s0 = 0.f, s1 = 0.f;
#pragma unroll
    for (int i = 0; i < 32; i++) {
        acc[i][0] = __expf((acc[i][0] - mx0) * SCALE);
        acc[i][1] = __expf((acc[i][1] - mx0) * SCALE);
        acc[i][2] = __expf((acc[i][2] - mx1) * SCALE);
        acc[i][3] = __expf((acc[i][3] - mx1) * SCALE);
        s0 += acc[i][0] + acc[i][1];
        s1 += acc[i][2] + acc[i][3];
    }
    s0 += __shfl_xor_sync(~0u, s0, 1); s0 += __shfl_xor_sync(~0u, s0, 2);
    s1 += __shfl_xor_sync(~0u, s1, 1); s1 += __shfl_xor_sync(~0u, s1, 2);
    const float inv0 = 1.f / s0, inv1 = 1.f / s1;

    // convert P to fp16 A-fragments in-register
    uint32_t pa[16][4];
#pragma unroll
    for (int k2 = 0; k2 < 16; k2++) {
        pa[k2][0] = packh2(acc[2*k2][0]   * inv0, acc[2*k2][1]   * inv0);
        pa[k2][1] = packh2(acc[2*k2][2]   * inv1, acc[2*k2][3]   * inv1);
        pa[k2][2] = packh2(acc[2*k2+1][0] * inv0, acc[2*k2+1][1] * inv0);
        pa[k2][3] = packh2(acc[2*k2+1][2] * inv1, acc[2*k2+1][3] * inv1);
    }

    asm volatile("cp.async.wait_group 0;");
    __syncthreads();

    // ctx = P @ V  (V rows = output dim d2, cols = k2)
    float o[16][4];
#pragma unroll
    for (int i = 0; i < 16; i++)
        o[i][0] = o[i][1] = o[i][2] = o[i][3] = 0.f;
#pragma unroll
    for (int k2 = 0; k2 < 16; k2++) {
#pragma unroll
        for (int p = 0; p < 8; p++) {
            uint32_t b0, b1, b2, b3;
            LDSM4(b0, b1, b2, b3, bBV + (uint32_t)(p * 16 * PADV * 2) + k2 * 32);
            MMA(o[2*p],   pa[k2][0], pa[k2][1], pa[k2][2], pa[k2][3], b0, b1);
            MMA(o[2*p+1], pa[k2][0], pa[k2][1], pa[k2][2], pa[k2][3], b2, b3);
        }
    }

    // fused rearrange epilogue
    const int b = t >> 8, h = (t >> 4) & 15, n = t & 15;
    __half* cbase = ca + ((long)(b * 4096 + h * 256)) * HID + n * 128;
    const int g = lane >> 2, tg = lane & 3;
    const int r0 = mh * 128 + w * 16 + g;
#pragma unroll
    for (int ni = 0; ni < 16; ni++) {
        int col = ni * 8 + 2 * tg;
        *(__half2*)(cbase + (long)r0 * HID + col)       = __floats2half2_rn(o[ni][0], o[ni][1]);
        *(__half2*)(cbase + (long)(r0 + 8) * HID + col) = __floats2half2_rn(o[ni][2], o[ni][3]);
    }
}

// ---------------- small kernels ----------------------------------------------
__global__ void conv_f16(const float* __restrict__ in, __half* __restrict__ out, int n4)
{
    int i = blockIdx.x * 256 + threadIdx.x;
    if (i < n4) {
        float4 v = ((const float4*)in)[i];
        ((__half2*)out)[2 * i]     = __floats2half2_rn(v.x, v.y);
        ((__half2*)out)[2 * i + 1] = __floats2half2_rn(v.z, v.w);
    }
}

__global__ void gather_bias(const float* b0, const float* b1, const float* b2,
                            float* __restrict__ out)
{
    int i = blockIdx.x * 256 + threadIdx.x;   // 0..6143
    const float* src = (i < 2048) ? b0 : (i < 4096) ? b1 : b2;
    out[i] = src[i & 2047];
}

// z: 0..4095; which = z>>11 (0=q,1=k)
__global__ void repack_qk(const __half* __restrict__ qkv,
                          __half* __restrict__ qp, __half* __restrict__ kp)
{
    __shared__ __half tile[32][34];
    const int bz = blockIdx.z;
    const int which = bz >> 11;
    const int z = bz & 2047;
    const int j = z & 1, n = (z >> 1) & 15, h = (z >> 5) & 15, b = z >> 9;
    const __half* ib = qkv + (long)which * MTOK * HID
                     + ((long)(b * S_ + n * 256 + j * 128)) * HID + h * 128;
    __half* ob = (which ? kp : qp) + (long)((b * 16 + h) * 16 + n) * (P_ * D_);
    const int d0 = blockIdx.x * 32, r0 = blockIdx.y * 32;
    const int tx = threadIdx.x, ty = threadIdx.y;
#pragma unroll
    for (int i = 0; i < 32; i += 8)
        tile[ty + i][tx] = ib[(long)(r0 + ty + i) * HID + d0 + tx];
    __syncthreads();
#pragma unroll
    for (int i = 0; i < 32; i += 8)
        ob[(long)(2 * (d0 + ty + i) + j) * D_ + r0 + tx] = tile[tx][ty + i];
}

__global__ void repack_v(const __half* __restrict__ in, __half* __restrict__ out)
{
    const int bz = blockIdx.y;
    const int j = bz & 1, n = (bz >> 1) & 15, h = (bz >> 5) & 15, b = bz >> 9;
    const int idx = blockIdx.x * 256 + threadIdx.x;
    const int r = idx >> 7, d = idx & 127;
    const __half* ib = in + ((long)(b * S_ + n * 256 + j * 128)) * HID + h * 128;
    long t = (b * 16 + h) * 16 + n;
    out[t * (long)(D_ * P_) + (long)r * P_ + 2 * d + j] = ib[(long)r * HID + d];
}

// ---------------- launch -------------------------------------------------------
extern "C" void kernel_launch(void* const* d_in, const int* in_sizes, int n_in,
                              void* d_out, int out_size)
{
    const float* X  = (const float*)d_in[0];
    const float* Wq = (const float*)d_in[1];
    const float* bq = (const float*)d_in[2];
    const float* Wk = (const float*)d_in[3];
    const float* bk = (const float*)d_in[4];
    const float* Wv = (const float*)d_in[5];
    const float* bv = (const float*)d_in[6];
    const float* Wo = (const float*)d_in[7];
    const float* bo = (const float*)d_in[8];
    float* out = (float*)d_out;

    __half *xh, *wh, *qkv, *qp, *kp, *vpt, *ca;
    float *bias;
    cudaGetSymbolAddress((void**)&xh,   g_xh);
    cudaGetSymbolAddress((void**)&wh,   g_wh);
    cudaGetSymbolAddress((void**)&bias, g_bias);
    cudaGetSymbolAddress((void**)&qkv,  g_qkv);
    cudaGetSymbolAddress((void**)&qp,   g_qp);
    cudaGetSymbolAddress((void**)&kp,   g_kp);
    cudaGetSymbolAddress((void**)&vpt,  g_vpt);
    cudaGetSymbolAddress((void**)&ca,   g_ca);

    cudaFuncSetAttribute(attn_fused, cudaFuncAttributeMaxDynamicSharedMemorySize, ATT_SMEM);

    const long WSZ = (long)HID * HID;

    conv_f16<<<(MTOK * HID / 4 + 255) / 256, 256>>>(X, xh, MTOK * HID / 4);
    conv_f16<<<(int)(WSZ / 4 + 255) / 256, 256>>>(Wq, wh + 0 * WSZ, (int)(WSZ / 4));
    conv_f16<<<(int)(WSZ / 4 + 255) / 256, 256>>>(Wk, wh + 1 * WSZ, (int)(WSZ / 4));
    conv_f16<<<(int)(WSZ / 4 + 255) / 256, 256>>>(Wv, wh + 2 * WSZ, (int)(WSZ / 4));
    conv_f16<<<(int)(WSZ / 4 + 255) / 256, 256>>>(Wo, wh + 3 * WSZ, (int)(WSZ / 4));
    gather_bias<<<24, 256>>>(bq, bk, bv, bias);

    // QKV projections: one batched launch, z = 0,1,2
    gemm_fp16<true><<<dim3(16, 128, 3), 256>>>(xh, wh, bias, qkv,
                                               HID, HID, HID, HID,
                                               0, WSZ, HID, (long)MTOK * HID, 1.f);

    repack_qk<<<dim3(4, 4, 4096), dim3(32, 8)>>>(qkv, qp, kp);
    repack_v <<<dim3(64, 2048), 256>>>(qkv + 2 * (long)MTOK * HID, vpt);

    // fused attention (scores + softmax + PV + rearrange)
    attn_fused<<<dim3(2, NT), 256, ATT_SMEM>>>(qp, kp, vpt, ca);

    // output projection
    gemm_fp16<false><<<dim3(16, 128, 1), 256>>>(ca, wh + 3 * WSZ, bo, out,
                                                HID, HID, HID, HID,
                                                0, 0, 0, 0, 1.f);
}

// round 7
// speedup vs baseline: 7.1325x; 1.0819x over previous
#include <cuda_runtime.h>
#include <cuda_fp16.h>
#include <stdint.h>

#define HID  2048
#define B_   4
#define S_   4096
#define P_   256
#define D_   128
#define NT   1024
#define MTOK 16384
#define SCALE 0.08838834764831845f

// ---------------- scratch ----------------------------------------------------
__device__ __half g_xh [(long)MTOK*HID];
__device__ __half g_wh [4][(long)HID*HID];
__device__ __half g_qkv[3][(long)MTOK*HID];
__device__ __half g_ca [(long)MTOK*HID];

__device__ __forceinline__ void cpa16(uint32_t d, const void* g) {
    asm volatile("cp.async.cg.shared.global [%0], [%1], 16;" :: "r"(d), "l"(g));
}
__device__ __forceinline__ uint32_t packh2(float a, float b) {
    __half2 h = __floats2half2_rn(a, b);
    return *(uint32_t*)&h;
}

#define LDSM4(r0,r1,r2,r3, addr) \
    asm volatile("ldmatrix.sync.aligned.m8n8.x4.shared.b16 {%0,%1,%2,%3}, [%4];" \
        : "=r"(r0), "=r"(r1), "=r"(r2), "=r"(r3) : "r"(addr))

#define LDSM4T(r0,r1,r2,r3, addr) \
    asm volatile("ldmatrix.sync.aligned.m8n8.x4.trans.shared.b16 {%0,%1,%2,%3}, [%4];" \
        : "=r"(r0), "=r"(r1), "=r"(r2), "=r"(r3) : "r"(addr))

#define MMA(d, a0,a1,a2,a3, b0,b1) \
    asm volatile("mma.sync.aligned.m16n8k16.row.col.f32.f16.f16.f32 " \
        "{%0,%1,%2,%3}, {%4,%5,%6,%7}, {%8,%9}, {%0,%1,%2,%3};" \
        : "+f"((d)[0]), "+f"((d)[1]), "+f"((d)[2]), "+f"((d)[3]) \
        : "r"(a0), "r"(a1), "r"(a2), "r"(a3), "r"(b0), "r"(b1))

// ---------------- FP16 GEMM: C = A @ W_z^T + bias_z --------------------------
// M=16384, N=2048 per z, K=2048, all ld = HID. z folded into gridDim.x.
#define PADH 40
#define BUFH (128 * PADH)

template<bool OUT_HALF>
__global__ __launch_bounds__(256, 2)
void gemm_fp16(const __half* __restrict__ A, const __half* __restrict__ Wbase,
               const float* __restrict__ bias0, const float* __restrict__ bias1,
               const float* __restrict__ bias2, void* __restrict__ Cv,
               long sW, long sC)
{
    __shared__ __half As[2 * BUFH];
    __shared__ __half Bs[2 * BUFH];

    const int z  = blockIdx.x >> 4;
    const int n0 = (blockIdx.x & 15) * 128;
    const int m0 = blockIdx.y * 128;
    const __half* Bm = Wbase + (long)z * sW;
    const float* bias = (z == 0) ? bias0 : (z == 1) ? bias1 : bias2;

    const int tid  = threadIdx.x;
    const int lane = tid & 31;
    const int wid  = tid >> 5;
    const int wm   = wid >> 2;
    const int wn   = wid & 3;
    const int g    = lane >> 2;
    const int tg   = lane & 3;

    float acc[4][4][4];
#pragma unroll
    for (int i = 0; i < 4; i++)
#pragma unroll
        for (int j = 0; j < 4; j++)
#pragma unroll
            for (int r = 0; r < 4; r++) acc[i][j][r] = 0.f;

    const uint32_t sA0 = (uint32_t)__cvta_generic_to_shared(As);
    const uint32_t sB0 = (uint32_t)__cvta_generic_to_shared(Bs);
    const uint32_t aBase = sA0 + (((wm * 64 + (lane & 15)) * PADH) + (lane >> 4) * 8) * 2;
    const uint32_t bBase = sB0 + (((wn * 32 + (lane & 7) + ((lane >> 4) << 3)) * PADH)
                                  + ((lane >> 3) & 1) * 8) * 2;

    auto prefetch = [&](int kt, int buf) {
#pragma unroll
        for (int u = 0; u < 2; u++) {
            int id   = tid + u * 256;
            int row  = id >> 2;
            int col8 = (id & 3) << 3;
            const __half* ga = A  + (long)(m0 + row) * HID + kt * 32 + col8;
            const __half* gb = Bm + (long)(n0 + row) * HID + kt * 32 + col8;
            cpa16((uint32_t)__cvta_generic_to_shared(&As[buf * BUFH + row * PADH + col8]), ga);
            cpa16((uint32_t)__cvta_generic_to_shared(&Bs[buf * BUFH + row * PADH + col8]), gb);
        }
        asm volatile("cp.async.commit_group;");
    };

    prefetch(0, 0);

    const int nK = HID >> 5;
    for (int t = 0; t < nK; t++) {
        if (t + 1 < nK) {
            prefetch(t + 1, (t + 1) & 1);
            asm volatile("cp.async.wait_group 1;");
        } else {
            asm volatile("cp.async.wait_group 0;");
        }
        __syncthreads();

        const uint32_t bufOff = (uint32_t)((t & 1) * BUFH * 2);

#pragma unroll
        for (int k0 = 0; k0 < 32; k0 += 16) {
            uint32_t af[4][4], bf[4][2];
            const uint32_t ak = aBase + bufOff + k0 * 2;
            const uint32_t bk = bBase + bufOff + k0 * 2;
#pragma unroll
            for (int mi = 0; mi < 4; mi++)
                LDSM4(af[mi][0], af[mi][1], af[mi][2], af[mi][3],
                      ak + (uint32_t)(mi * 16 * PADH * 2));
#pragma unroll
            for (int p = 0; p < 2; p++)
                LDSM4(bf[2*p][0], bf[2*p][1], bf[2*p+1][0], bf[2*p+1][1],
                      bk + (uint32_t)(p * 16 * PADH * 2));
#pragma unroll
            for (int mi = 0; mi < 4; mi++)
#pragma unroll
                for (int ni = 0; ni < 4; ni++)
                    MMA(acc[mi][ni], af[mi][0], af[mi][1], af[mi][2], af[mi][3],
                        bf[ni][0], bf[ni][1]);
        }
        __syncthreads();
    }

    const long cOff = (long)z * sC;
#pragma unroll
    for (int mi = 0; mi < 4; mi++) {
#pragma unroll
        for (int ni = 0; ni < 4; ni++) {
            int row = m0 + wm * 64 + mi * 16 + g;
            int col = n0 + wn * 32 + ni * 8 + 2 * tg;
            float b0 = bias[col], b1 = bias[col + 1];
            float v00 = acc[mi][ni][0] + b0;
            float v01 = acc[mi][ni][1] + b1;
            float v10 = acc[mi][ni][2] + b0;
            float v11 = acc[mi][ni][3] + b1;
            if (OUT_HALF) {
                __half* C = (__half*)Cv + cOff;
                *(__half2*)(C + (long)row * HID + col)       = __floats2half2_rn(v00, v01);
                *(__half2*)(C + (long)(row + 8) * HID + col) = __floats2half2_rn(v10, v11);
            } else {
                float* C = (float*)Cv + cOff;
                *(float2*)(C + (long)row * HID + col)       = make_float2(v00, v01);
                *(float2*)(C + (long)(row + 8) * HID + col) = make_float2(v10, v11);
            }
        }
    }
}

// ---------------- fused attention, direct load from g_qkv --------------------
// S[p2=2dq+jq][k2=2dk+jk] = sum_r qh[jq*128+r][h*128+dq] * kh[jk*128+r][h*128+dk]
// ctx[p2][d2] = sum_{dk,jk} P[p2][2dk+jk] * vh[jk*128+d2][h*128+dk]
// grid (2, NT): x = mh (dq half), y = t. 8 warps: jq = w>>2, q = w&3 (dq 16-block).
#define PADQ 72
#define PADK 136
#define PADV 136
#define ATT_SMEM ((256*PADQ + 256*PADK + 256*PADV) * 2)   // 176128

__global__ __launch_bounds__(256, 1)
void attn_fused(const __half* __restrict__ qkv, __half* __restrict__ ca)
{
    extern __shared__ __half smn[];
    const int t = blockIdx.y, mh = blockIdx.x;
    const int b = t >> 8, h = (t >> 4) & 15, n = t & 15;
    const int tid = threadIdx.x, lane = tid & 31, w = tid >> 5;
    const int jq = w >> 2, q = w & 3;

    const long rowbase = (long)(b * S_ + n * 256) * HID;
    const __half* qg = qkv + rowbase + h * 128 + mh * 64;
    const __half* kg = qkv + (long)MTOK * HID + rowbase + h * 128;
    const __half* vg = qkv + 2 * (long)MTOK * HID + rowbase + h * 128;

    const uint32_t qsu = (uint32_t)__cvta_generic_to_shared(smn);
    const uint32_t ksu = qsu + 256 * PADQ * 2;
    const uint32_t vsu = ksu + 256 * PADK * 2;

    // G0: Q (256 x 64) + K rows r=0..63 both jk (rows 0-63, 128-191)
#pragma unroll
    for (int u = 0; u < 8; u++) {
        int id = tid + u * 256, row = id >> 3, seg = id & 7;
        cpa16(qsu + (row * PADQ + seg * 8) * 2, qg + (long)row * HID + seg * 8);
    }
#pragma unroll
    for (int u = 0; u < 8; u++) {
        int id = tid + u * 256, rr = id >> 4, seg = id & 15;
        int row = (rr & 63) + (rr >> 6) * 128;
        cpa16(ksu + (row * PADK + seg * 8) * 2, kg + (long)row * HID + seg * 8);
    }
    asm volatile("cp.async.commit_group;");
    // G1: K rows r=64..127 both jk
#pragma unroll
    for (int u = 0; u < 8; u++) {
        int id = tid + u * 256, rr = id >> 4, seg = id & 15;
        int row = 64 + (rr & 63) + (rr >> 6) * 128;
        cpa16(ksu + (row * PADK + seg * 8) * 2, kg + (long)row * HID + seg * 8);
    }
    asm volatile("cp.async.commit_group;");
    // G2: V (256 x 128)
#pragma unroll
    for (int u = 0; u < 16; u++) {
        int id = tid + u * 256, row = id >> 4, seg = id & 15;
        cpa16(vsu + (row * PADV + seg * 8) * 2, vg + (long)row * HID + seg * 8);
    }
    asm volatile("cp.async.commit_group;");

    // fragment bases
    const uint32_t aB = qsu + (((jq * 128 + (lane & 7) + ((lane >> 4) & 1) * 8) * PADQ)
                               + q * 16 + ((lane >> 3) & 1) * 8) * 2;
    const uint32_t kB = ksu + ((((lane & 7) + ((lane >> 3) & 1) * 8) * PADK)
                               + (lane >> 4) * 8) * 2;
    const uint32_t vB = vsu + ((((lane & 7) + ((lane >> 4) & 1) * 8) * PADV)
                               + ((lane >> 3) & 1) * 8) * 2;

    float acc[32][4];
#pragma unroll
    for (int i = 0; i < 32; i++)
        acc[i][0] = acc[i][1] = acc[i][2] = acc[i][3] = 0.f;

    asm volatile("cp.async.wait_group 2;");
    __syncthreads();

    // preload Q A-fragments (trans): m=dq16, k=r16 per step
    uint32_t qa[8][4];
#pragma unroll
    for (int kk = 0; kk < 8; kk++)
        LDSM4T(qa[kk][0], qa[kk][1], qa[kk][2], qa[kk][3],
               aB + (uint32_t)(kk * 16 * PADQ * 2));

    // S = Qslab^T @ Kslab, contraction over r
#pragma unroll
    for (int kk = 0; kk < 8; kk++) {
        if (kk == 4) { asm volatile("cp.async.wait_group 1;"); __syncthreads(); }
#pragma unroll
        for (int jk = 0; jk < 2; jk++) {
#pragma unroll
            for (int p = 0; p < 8; p++) {
                uint32_t b0, b1, b2, b3;
                LDSM4T(b0, b1, b2, b3,
                       kB + (uint32_t)(((jk * 128 + kk * 16) * PADK + p * 16) * 2));
                MMA(acc[jk*16 + 2*p],     qa[kk][0], qa[kk][1], qa[kk][2], qa[kk][3], b0, b1);
                MMA(acc[jk*16 + 2*p + 1], qa[kk][0], qa[kk][1], qa[kk][2], qa[kk][3], b2, b3);
            }
        }
    }

    // softmax: row g -> regs 0,1 ; row g+8 -> regs 2,3 (full 256 cols in-warp)
    float mx0 = -1e30f, mx1 = -1e30f;
#pragma unroll
    for (int i = 0; i < 32; i++) {
        mx0 = fmaxf(mx0, fmaxf(acc[i][0], acc[i][1]));
        mx1 = fmaxf(mx1, fmaxf(acc[i][2], acc[i][3]));
    }
    mx0 = fmaxf(mx0, __shfl_xor_sync(~0u, mx0, 1));
    mx0 = fmaxf(mx0, __shfl_xor_sync(~0u, mx0, 2));
    mx1 = fmaxf(mx1, __shfl_xor_sync(~0u, mx1, 1));
    mx1 = fmaxf(mx1, __shfl_xor_sync(~0u, mx1, 2));
    float s0 = 0.f, s1 = 0.f;
#pragma unroll
    for (int i = 0; i < 32; i++) {
        acc[i][0] = __expf((acc[i][0] - mx0) * SCALE);
        acc[i][1] = __expf((acc[i][1] - mx0) * SCALE);
        acc[i][2] = __expf((acc[i][2] - mx1) * SCALE);
        acc[i][3] = __expf((acc[i][3] - mx1) * SCALE);
        s0 += acc[i][0] + acc[i][1];
        s1 += acc[i][2] + acc[i][3];
    }
    s0 += __shfl_xor_sync(~0u, s0, 1); s0 += __shfl_xor_sync(~0u, s0, 2);
    s1 += __shfl_xor_sync(~0u, s1, 1); s1 += __shfl_xor_sync(~0u, s1, 2);
    const float inv0 = 1.f / s0, inv1 = 1.f / s1;

    asm volatile("cp.async.wait_group 0;");
    __syncthreads();

    // ctx = P @ V : per jk, A = P fragments (in-register), B = Vs natural layout
    float o[16][4];
#pragma unroll
    for (int i = 0; i < 16; i++)
        o[i][0] = o[i][1] = o[i][2] = o[i][3] = 0.f;

#pragma unroll
    for (int jk = 0; jk < 2; jk++) {
#pragma unroll
        for (int kk2 = 0; kk2 < 8; kk2++) {
            const int t0 = jk * 16 + 2 * kk2, t1 = t0 + 1;
            uint32_t a0 = packh2(acc[t0][0] * inv0, acc[t0][1] * inv0);
            uint32_t a1 = packh2(acc[t0][2] * inv1, acc[t0][3] * inv1);
            uint32_t a2 = packh2(acc[t1][0] * inv0, acc[t1][1] * inv0);
            uint32_t a3 = packh2(acc[t1][2] * inv1, acc[t1][3] * inv1);
#pragma unroll
            for (int p2 = 0; p2 < 8; p2++) {
                uint32_t b0, b1, b2, b3;
                LDSM4(b0, b1, b2, b3,
                      vB + (uint32_t)((((jk * 128 + p2 * 16) * PADV) + kk2 * 16) * 2));
                MMA(o[2*p2],     a0, a1, a2, a3, b0, b1);
                MMA(o[2*p2 + 1], a0, a1, a2, a3, b2, b3);
            }
        }
    }

    // epilogue: ca[(b*4096 + h*256 + p2)*HID + n*128 + d2]
    const int g = lane >> 2, tg = lane & 3;
    const int p2row = 2 * (mh * 64 + q * 16 + g) + jq;
    __half* cbase = ca + ((long)(b * 4096 + h * 256)) * HID + n * 128;
#pragma unroll
    for (int ni = 0; ni < 16; ni++) {
        int d2 = ni * 8 + 2 * tg;
        *(__half2*)(cbase + (long)p2row * HID + d2)        = __floats2half2_rn(o[ni][0], o[ni][1]);
        *(__half2*)(cbase + (long)(p2row + 16) * HID + d2) = __floats2half2_rn(o[ni][2], o[ni][3]);
    }
}

// ---------------- f32 -> f16 conversion --------------------------------------
__global__ void conv_f16(const float* __restrict__ in, __half* __restrict__ out, int n4)
{
    int i = blockIdx.x * 256 + threadIdx.x;
    if (i < n4) {
        float4 v = ((const float4*)in)[i];
        ((__half2*)out)[2 * i]     = __floats2half2_rn(v.x, v.y);
        ((__half2*)out)[2 * i + 1] = __floats2half2_rn(v.z, v.w);
    }
}

// ---------------- launch -------------------------------------------------------
extern "C" void kernel_launch(void* const* d_in, const int* in_sizes, int n_in,
                              void* d_out, int out_size)
{
    const float* X  = (const float*)d_in[0];
    const float* Wq = (const float*)d_in[1];
    const float* bq = (const float*)d_in[2];
    const float* Wk = (const float*)d_in[3];
    const float* bk = (const float*)d_in[4];
    const float* Wv = (const float*)d_in[5];
    const float* bv = (const float*)d_in[6];
    const float* Wo = (const float*)d_in[7];
    const float* bo = (const float*)d_in[8];
    float* out = (float*)d_out;

    __half *xh, *wh, *qkv, *ca;
    cudaGetSymbolAddress((void**)&xh,  g_xh);
    cudaGetSymbolAddress((void**)&wh,  g_wh);
    cudaGetSymbolAddress((void**)&qkv, g_qkv);
    cudaGetSymbolAddress((void**)&ca,  g_ca);

    cudaFuncSetAttribute(attn_fused, cudaFuncAttributeMaxDynamicSharedMemorySize, ATT_SMEM);

    const long WSZ = (long)HID * HID;

    // launches 1-5 (so ncu -s 5 captures the QKV GEMM)
    conv_f16<<<(MTOK * HID / 4 + 255) / 256, 256>>>(X, xh, MTOK * HID / 4);
    conv_f16<<<(int)(WSZ / 4 + 255) / 256, 256>>>(Wq, wh + 0 * WSZ, (int)(WSZ / 4));
    conv_f16<<<(int)(WSZ / 4 + 255) / 256, 256>>>(Wk, wh + 1 * WSZ, (int)(WSZ / 4));
    conv_f16<<<(int)(WSZ / 4 + 255) / 256, 256>>>(Wv, wh + 2 * WSZ, (int)(WSZ / 4));
    conv_f16<<<(int)(WSZ / 4 + 255) / 256, 256>>>(Wo, wh + 3 * WSZ, (int)(WSZ / 4));

    // QKV projections: z folded into grid.x (L2 reuse of A row-blocks)
    gemm_fp16<true><<<dim3(48, 128), 256>>>(xh, wh, bq, bk, bv, qkv,
                                            WSZ, (long)MTOK * HID);

    // fused attention: direct-load, scores+softmax+PV+rearrange
    attn_fused<<<dim3(2, NT), 256, ATT_SMEM>>>(qkv, ca);

    // output projection
    gemm_fp16<false><<<dim3(16, 128), 256>>>(ca, wh + 3 * WSZ, bo, bo, bo, out,
                                             0, 0);
}

// round 8
// speedup vs baseline: 7.3815x; 1.0349x over previous
#include <cuda_runtime.h>
#include <cuda_fp16.h>
#include <stdint.h>

#define HID  2048
#define B_   4
#define S_   4096
#define P_   256
#define D_   128
#define NT   1024
#define MTOK 16384
#define SCALE 0.08838834764831845f

// ---------------- scratch ----------------------------------------------------
__device__ __half g_xh [(long)MTOK*HID];
__device__ __half g_wh [4][(long)HID*HID];
__device__ __half g_qkv[3][(long)MTOK*HID];
__device__ __half g_ca [(long)MTOK*HID];

__device__ __forceinline__ void cpa16(uint32_t d, const void* g) {
    asm volatile("cp.async.cg.shared.global [%0], [%1], 16;" :: "r"(d), "l"(g));
}
__device__ __forceinline__ uint32_t packh2(float a, float b) {
    __half2 h = __floats2half2_rn(a, b);
    return *(uint32_t*)&h;
}

#define LDSM4(r0,r1,r2,r3, addr) \
    asm volatile("ldmatrix.sync.aligned.m8n8.x4.shared.b16 {%0,%1,%2,%3}, [%4];" \
        : "=r"(r0), "=r"(r1), "=r"(r2), "=r"(r3) : "r"(addr))

#define LDSM4T(r0,r1,r2,r3, addr) \
    asm volatile("ldmatrix.sync.aligned.m8n8.x4.trans.shared.b16 {%0,%1,%2,%3}, [%4];" \
        : "=r"(r0), "=r"(r1), "=r"(r2), "=r"(r3) : "r"(addr))

#define MMA(d, a0,a1,a2,a3, b0,b1) \
    asm volatile("mma.sync.aligned.m16n8k16.row.col.f32.f16.f16.f32 " \
        "{%0,%1,%2,%3}, {%4,%5,%6,%7}, {%8,%9}, {%0,%1,%2,%3};" \
        : "+f"((d)[0]), "+f"((d)[1]), "+f"((d)[2]), "+f"((d)[3]) \
        : "r"(a0), "r"(a1), "r"(a2), "r"(a3), "r"(b0), "r"(b1))

// ---------------- FP16 GEMM: C = A @ W_z^T + bias_z --------------------------
// M=16384, N=2048/z, K=2048, ld = HID. z folded into gridDim.x.
// 3-stage cp.async pipeline, ONE barrier per K-tile.
#define PADH 40
#define BUFH (128 * PADH)
#define GEMM_SMEM (6 * BUFH * 2)   // 3 stages x (A+B) x 10KB = 61440 B

template<bool OUT_HALF>
__global__ __launch_bounds__(256, 2)
void gemm_fp16(const __half* __restrict__ A, const __half* __restrict__ Wbase,
               const float* __restrict__ bias0, const float* __restrict__ bias1,
               const float* __restrict__ bias2, void* __restrict__ Cv,
               long sW, long sC)
{
    extern __shared__ __half sgm[];
    __half* As = sgm;              // [3][BUFH]
    __half* Bs = sgm + 3 * BUFH;   // [3][BUFH]

    const int z  = blockIdx.x >> 4;
    const int n0 = (blockIdx.x & 15) * 128;
    const int m0 = blockIdx.y * 128;
    const __half* Bm = Wbase + (long)z * sW;
    const float* bias = (z == 0) ? bias0 : (z == 1) ? bias1 : bias2;

    const int tid  = threadIdx.x;
    const int lane = tid & 31;
    const int wid  = tid >> 5;
    const int wm   = wid >> 2;
    const int wn   = wid & 3;
    const int g    = lane >> 2;
    const int tg   = lane & 3;

    float acc[4][4][4];
#pragma unroll
    for (int i = 0; i < 4; i++)
#pragma unroll
        for (int j = 0; j < 4; j++)
#pragma unroll
            for (int r = 0; r < 4; r++) acc[i][j][r] = 0.f;

    const uint32_t sA0 = (uint32_t)__cvta_generic_to_shared(As);
    const uint32_t sB0 = (uint32_t)__cvta_generic_to_shared(Bs);
    const uint32_t aBase = sA0 + (((wm * 64 + (lane & 15)) * PADH) + (lane >> 4) * 8) * 2;
    const uint32_t bBase = sB0 + (((wn * 32 + (lane & 7) + ((lane >> 4) << 3)) * PADH)
                                  + ((lane >> 3) & 1) * 8) * 2;

    auto prefetch = [&](int kt, int buf) {
#pragma unroll
        for (int u = 0; u < 2; u++) {
            int id   = tid + u * 256;
            int row  = id >> 2;
            int col8 = (id & 3) << 3;
            const __half* ga = A  + (long)(m0 + row) * HID + kt * 32 + col8;
            const __half* gb = Bm + (long)(n0 + row) * HID + kt * 32 + col8;
            cpa16((uint32_t)__cvta_generic_to_shared(&As[buf * BUFH + row * PADH + col8]), ga);
            cpa16((uint32_t)__cvta_generic_to_shared(&Bs[buf * BUFH + row * PADH + col8]), gb);
        }
        asm volatile("cp.async.commit_group;");
    };

    prefetch(0, 0);
    prefetch(1, 1);

    const int nK = HID >> 5;
    int buf = 0, pbuf = 2;
    for (int t = 0; t < nK; t++) {
        // wait for buffer t; allow the (t+1) load to stay in flight
        if (t + 1 < nK) asm volatile("cp.async.wait_group 1;");
        else            asm volatile("cp.async.wait_group 0;");
        __syncthreads();   // also guards prefetch below against compute(t-1) readers

        if (t + 2 < nK) prefetch(t + 2, pbuf);

        const uint32_t bufOff = (uint32_t)(buf * BUFH * 2);
#pragma unroll
        for (int k0 = 0; k0 < 32; k0 += 16) {
            uint32_t af[4][4], bf[4][2];
            const uint32_t ak = aBase + bufOff + k0 * 2;
            const uint32_t bk = bBase + bufOff + k0 * 2;
#pragma unroll
            for (int mi = 0; mi < 4; mi++)
                LDSM4(af[mi][0], af[mi][1], af[mi][2], af[mi][3],
                      ak + (uint32_t)(mi * 16 * PADH * 2));
#pragma unroll
            for (int p = 0; p < 2; p++)
                LDSM4(bf[2*p][0], bf[2*p][1], bf[2*p+1][0], bf[2*p+1][1],
                      bk + (uint32_t)(p * 16 * PADH * 2));
#pragma unroll
            for (int mi = 0; mi < 4; mi++)
#pragma unroll
                for (int ni = 0; ni < 4; ni++)
                    MMA(acc[mi][ni], af[mi][0], af[mi][1], af[mi][2], af[mi][3],
                        bf[ni][0], bf[ni][1]);
        }
        buf  = (buf  == 2) ? 0 : buf  + 1;
        pbuf = (pbuf == 2) ? 0 : pbuf + 1;
    }

    const long cOff = (long)z * sC;
#pragma unroll
    for (int mi = 0; mi < 4; mi++) {
#pragma unroll
        for (int ni = 0; ni < 4; ni++) {
            int row = m0 + wm * 64 + mi * 16 + g;
            int col = n0 + wn * 32 + ni * 8 + 2 * tg;
            float b0 = bias[col], b1 = bias[col + 1];
            float v00 = acc[mi][ni][0] + b0;
            float v01 = acc[mi][ni][1] + b1;
            float v10 = acc[mi][ni][2] + b0;
            float v11 = acc[mi][ni][3] + b1;
            if (OUT_HALF) {
                __half* C = (__half*)Cv + cOff;
                *(__half2*)(C + (long)row * HID + col)       = __floats2half2_rn(v00, v01);
                *(__half2*)(C + (long)(row + 8) * HID + col) = __floats2half2_rn(v10, v11);
            } else {
                float* C = (float*)Cv + cOff;
                *(float2*)(C + (long)row * HID + col)       = make_float2(v00, v01);
                *(float2*)(C + (long)(row + 8) * HID + col) = make_float2(v10, v11);
            }
        }
    }
}

// ---------------- fused attention, direct load from g_qkv --------------------
#define PADQ 72
#define PADK 136
#define PADV 136
#define ATT_SMEM ((256*PADQ + 256*PADK + 256*PADV) * 2)   // 176128

__global__ __launch_bounds__(256, 1)
void attn_fused(const __half* __restrict__ qkv, __half* __restrict__ ca)
{
    extern __shared__ __half smn[];
    const int t = blockIdx.y, mh = blockIdx.x;
    const int b = t >> 8, h = (t >> 4) & 15, n = t & 15;
    const int tid = threadIdx.x, lane = tid & 31, w = tid >> 5;
    const int jq = w >> 2, q = w & 3;

    const long rowbase = (long)(b * S_ + n * 256) * HID;
    const __half* qg = qkv + rowbase + h * 128 + mh * 64;
    const __half* kg = qkv + (long)MTOK * HID + rowbase + h * 128;
    const __half* vg = qkv + 2 * (long)MTOK * HID + rowbase + h * 128;

    const uint32_t qsu = (uint32_t)__cvta_generic_to_shared(smn);
    const uint32_t ksu = qsu + 256 * PADQ * 2;
    const uint32_t vsu = ksu + 256 * PADK * 2;

    // G0: Q (256 x 64) + K rows r=0..63 both jk
#pragma unroll
    for (int u = 0; u < 8; u++) {
        int id = tid + u * 256, row = id >> 3, seg = id & 7;
        cpa16(qsu + (row * PADQ + seg * 8) * 2, qg + (long)row * HID + seg * 8);
    }
#pragma unroll
    for (int u = 0; u < 8; u++) {
        int id = tid + u * 256, rr = id >> 4, seg = id & 15;
        int row = (rr & 63) + (rr >> 6) * 128;
        cpa16(ksu + (row * PADK + seg * 8) * 2, kg + (long)row * HID + seg * 8);
    }
    asm volatile("cp.async.commit_group;");
    // G1: K rows r=64..127 both jk
#pragma unroll
    for (int u = 0; u < 8; u++) {
        int id = tid + u * 256, rr = id >> 4, seg = id & 15;
        int row = 64 + (rr & 63) + (rr >> 6) * 128;
        cpa16(ksu + (row * PADK + seg * 8) * 2, kg + (long)row * HID + seg * 8);
    }
    asm volatile("cp.async.commit_group;");
    // G2: V (256 x 128)
#pragma unroll
    for (int u = 0; u < 16; u++) {
        int id = tid + u * 256, row = id >> 4, seg = id & 15;
        cpa16(vsu + (row * PADV + seg * 8) * 2, vg + (long)row * HID + seg * 8);
    }
    asm volatile("cp.async.commit_group;");

    const uint32_t aB = qsu + (((jq * 128 + (lane & 7) + ((lane >> 4) & 1) * 8) * PADQ)
                               + q * 16 + ((lane >> 3) & 1) * 8) * 2;
    const uint32_t kB = ksu + ((((lane & 7) + ((lane >> 3) & 1) * 8) * PADK)
                               + (lane >> 4) * 8) * 2;
    const uint32_t vB = vsu + ((((lane & 7) + ((lane >> 4) & 1) * 8) * PADV)
                               + ((lane >> 3) & 1) * 8) * 2;

    float acc[32][4];
#pragma unroll
    for (int i = 0; i < 32; i++)
        acc[i][0] = acc[i][1] = acc[i][2] = acc[i][3] = 0.f;

    asm volatile("cp.async.wait_group 2;");
    __syncthreads();

    uint32_t qa[8][4];
#pragma unroll
    for (int kk = 0; kk < 8; kk++)
        LDSM4T(qa[kk][0], qa[kk][1], qa[kk][2], qa[kk][3],
               aB + (uint32_t)(kk * 16 * PADQ * 2));

#pragma unroll
    for (int kk = 0; kk < 8; kk++) {
        if (kk == 4) { asm volatile("cp.async.wait_group 1;"); __syncthreads(); }
#pragma unroll
        for (int jk = 0; jk < 2; jk++) {
#pragma unroll
            for (int p = 0; p < 8; p++) {
                uint32_t b0, b1, b2, b3;
                LDSM4T(b0, b1, b2, b3,
                       kB + (uint32_t)(((jk * 128 + kk * 16) * PADK + p * 16) * 2));
                MMA(acc[jk*16 + 2*p],     qa[kk][0], qa[kk][1], qa[kk][2], qa[kk][3], b0, b1);
                MMA(acc[jk*16 + 2*p + 1], qa[kk][0], qa[kk][1], qa[kk][2], qa[kk][3], b2, b3);
            }
        }
    }

    float mx0 = -1e30f, mx1 = -1e30f;
#pragma unroll
    for (int i = 0; i < 32; i++) {
        mx0 = fmaxf(mx0, fmaxf(acc[i][0], acc[i][1]));
        mx1 = fmaxf(mx1, fmaxf(acc[i][2], acc[i][3]));
    }
    mx0 = fmaxf(mx0, __shfl_xor_sync(~0u, mx0, 1));
    mx0 = fmaxf(mx0, __shfl_xor_sync(~0u, mx0, 2));
    mx1 = fmaxf(mx1, __shfl_xor_sync(~0u, mx1, 1));
    mx1 = fmaxf(mx1, __shfl_xor_sync(~0u, mx1, 2));
    float s0 = 0.f, s1 = 0.f;
#pragma unroll
    for (int i = 0; i < 32; i++) {
        acc[i][0] = __expf((acc[i][0] - mx0) * SCALE);
        acc[i][1] = __expf((acc[i][1] - mx0) * SCALE);
        acc[i][2] = __expf((acc[i][2] - mx1) * SCALE);
        acc[i][3] = __expf((acc[i][3] - mx1) * SCALE);
        s0 += acc[i][0] + acc[i][1];
        s1 += acc[i][2] + acc[i][3];
    }
    s0 += __shfl_xor_sync(~0u, s0, 1); s0 += __shfl_xor_sync(~0u, s0, 2);
    s1 += __shfl_xor_sync(~0u, s1, 1); s1 += __shfl_xor_sync(~0u, s1, 2);
    const float inv0 = 1.f / s0, inv1 = 1.f / s1;

    asm volatile("cp.async.wait_group 0;");
    __syncthreads();

    float o[16][4];
#pragma unroll
    for (int i = 0; i < 16; i++)
        o[i][0] = o[i][1] = o[i][2] = o[i][3] = 0.f;

#pragma unroll
    for (int jk = 0; jk < 2; jk++) {
#pragma unroll
        for (int kk2 = 0; kk2 < 8; kk2++) {
            const int t0 = jk * 16 + 2 * kk2, t1 = t0 + 1;
            uint32_t a0 = packh2(acc[t0][0] * inv0, acc[t0][1] * inv0);
            uint32_t a1 = packh2(acc[t0][2] * inv1, acc[t0][3] * inv1);
            uint32_t a2 = packh2(acc[t1][0] * inv0, acc[t1][1] * inv0);
            uint32_t a3 = packh2(acc[t1][2] * inv1, acc[t1][3] * inv1);
#pragma unroll
            for (int p2 = 0; p2 < 8; p2++) {
                uint32_t b0, b1, b2, b3;
                LDSM4(b0, b1, b2, b3,
                      vB + (uint32_t)((((jk * 128 + p2 * 16) * PADV) + kk2 * 16) * 2));
                MMA(o[2*p2],     a0, a1, a2, a3, b0, b1);
                MMA(o[2*p2 + 1], a0, a1, a2, a3, b2, b3);
            }
        }
    }

    const int g = lane >> 2, tg = lane & 3;
    const int p2row = 2 * (mh * 64 + q * 16 + g) + jq;
    __half* cbase = ca + ((long)(b * 4096 + h * 256)) * HID + n * 128;
#pragma unroll
    for (int ni = 0; ni < 16; ni++) {
        int d2 = ni * 8 + 2 * tg;
        *(__half2*)(cbase + (long)p2row * HID + d2)        = __floats2half2_rn(o[ni][0], o[ni][1]);
        *(__half2*)(cbase + (long)(p2row + 16) * HID + d2) = __floats2half2_rn(o[ni][2], o[ni][3]);
    }
}

// ---------------- fused f32->f16 conversion of X + all weights ---------------
#define XN4 ((long)MTOK * HID / 4)          // 8388608
#define WN4 ((long)HID * HID / 4)           // 1048576
__global__ void conv_all(const float* __restrict__ X,
                         const float* __restrict__ W0, const float* __restrict__ W1,
                         const float* __restrict__ W2, const float* __restrict__ W3,
                         __half* __restrict__ xh, __half* __restrict__ wh)
{
    long i = (long)blockIdx.x * 256 + threadIdx.x;
    const float* src;
    __half* dst;
    long idx;
    if (i < XN4) {
        src = X; dst = xh; idx = i;
    } else {
        long j = i - XN4;
        int wsel = (int)(j / WN4);
        src = (wsel == 0) ? W0 : (wsel == 1) ? W1 : (wsel == 2) ? W2 : W3;
        dst = wh + (long)wsel * (WN4 * 4);
        idx = j - (long)wsel * WN4;
    }
    float4 v = ((const float4*)src)[idx];
    ((__half2*)dst)[2 * idx]     = __floats2half2_rn(v.x, v.y);
    ((__half2*)dst)[2 * idx + 1] = __floats2half2_rn(v.z, v.w);
}

// ---------------- launch -------------------------------------------------------
extern "C" void kernel_launch(void* const* d_in, const int* in_sizes, int n_in,
                              void* d_out, int out_size)
{
    const float* X  = (const float*)d_in[0];
    const float* Wq = (const float*)d_in[1];
    const float* bq = (const float*)d_in[2];
    const float* Wk = (const float*)d_in[3];
    const float* bk = (const float*)d_in[4];
    const float* Wv = (const float*)d_in[5];
    const float* bv = (const float*)d_in[6];
    const float* Wo = (const float*)d_in[7];
    const float* bo = (const float*)d_in[8];
    float* out = (float*)d_out;

    __half *xh, *wh, *qkv, *ca;
    cudaGetSymbolAddress((void**)&xh,  g_xh);
    cudaGetSymbolAddress((void**)&wh,  g_wh);
    cudaGetSymbolAddress((void**)&qkv, g_qkv);
    cudaGetSymbolAddress((void**)&ca,  g_ca);

    cudaFuncSetAttribute(attn_fused, cudaFuncAttributeMaxDynamicSharedMemorySize, ATT_SMEM);
    cudaFuncSetAttribute(gemm_fp16<true>,  cudaFuncAttributeMaxDynamicSharedMemorySize, GEMM_SMEM);
    cudaFuncSetAttribute(gemm_fp16<false>, cudaFuncAttributeMaxDynamicSharedMemorySize, GEMM_SMEM);

    const long WSZ = (long)HID * HID;
    const long TOT4 = XN4 + 4 * WN4;   // 12582912 float4s

    // single conversion launch for X + Wq/Wk/Wv/Wo
    conv_all<<<(int)((TOT4 + 255) / 256), 256>>>(X, Wq, Wk, Wv, Wo, xh, wh);

    // QKV projections: z folded into grid.x (L2 reuse of A row-blocks)
    gemm_fp16<true><<<dim3(48, 128), 256, GEMM_SMEM>>>(xh, wh, bq, bk, bv, qkv,
                                                       WSZ, (long)MTOK * HID);

    // fused attention: direct-load, scores+softmax+PV+rearrange
    attn_fused<<<dim3(2, NT), 256, ATT_SMEM>>>(qkv, ca);

    // output projection
    gemm_fp16<false><<<dim3(16, 128), 256, GEMM_SMEM>>>(ca, wh + 3 * WSZ, bo, bo, bo, out,
                                                        0, 0);
}

// round 9
// speedup vs baseline: 8.3845x; 1.1359x over previous
#include <cuda_runtime.h>
#include <cuda_fp16.h>
#include <stdint.h>

#define HID  2048
#define B_   4
#define S_   4096
#define P_   256
#define D_   128
#define NT   1024
#define MTOK 16384
#define SCALE 0.08838834764831845f

// ---------------- scratch ----------------------------------------------------
__device__ __half g_xh [(long)MTOK*HID];
__device__ __half g_wh [4][(long)HID*HID];
__device__ __half g_qkv[3][(long)MTOK*HID];
__device__ __half g_ca [(long)MTOK*HID];

__device__ __forceinline__ void cpa16(uint32_t d, const void* g) {
    asm volatile("cp.async.cg.shared.global [%0], [%1], 16;" :: "r"(d), "l"(g));
}
__device__ __forceinline__ uint32_t packh2(float a, float b) {
    __half2 h = __floats2half2_rn(a, b);
    return *(uint32_t*)&h;
}

#define LDSM4(r0,r1,r2,r3, addr) \
    asm volatile("ldmatrix.sync.aligned.m8n8.x4.shared.b16 {%0,%1,%2,%3}, [%4];" \
        : "=r"(r0), "=r"(r1), "=r"(r2), "=r"(r3) : "r"(addr))

#define LDSM4T(r0,r1,r2,r3, addr) \
    asm volatile("ldmatrix.sync.aligned.m8n8.x4.trans.shared.b16 {%0,%1,%2,%3}, [%4];" \
        : "=r"(r0), "=r"(r1), "=r"(r2), "=r"(r3) : "r"(addr))

#define MMA(d, a0,a1,a2,a3, b0,b1) \
    asm volatile("mma.sync.aligned.m16n8k16.row.col.f32.f16.f16.f32 " \
        "{%0,%1,%2,%3}, {%4,%5,%6,%7}, {%8,%9}, {%0,%1,%2,%3};" \
        : "+f"((d)[0]), "+f"((d)[1]), "+f"((d)[2]), "+f"((d)[3]) \
        : "r"(a0), "r"(a1), "r"(a2), "r"(a3), "r"(b0), "r"(b1))

// ---------------- FP16 GEMM: C = A @ W_z^T + bias_z --------------------------
// M=16384, N=2048/z, K=2048. BK=64 (4 k16-steps per smem stage), 3 stages,
// ONE barrier per 64-K tile; ptxas pipelines LDSM(k+1) under MMA(k).
#define PADH 72
#define BUFH (128 * PADH)
#define GEMM_SMEM (6 * BUFH * 2)   // 3 stages x (A+B) x 18KB = 110592 B

template<bool OUT_HALF>
__global__ __launch_bounds__(256, 2)
void gemm_fp16(const __half* __restrict__ A, const __half* __restrict__ Wbase,
               const float* __restrict__ bias0, const float* __restrict__ bias1,
               const float* __restrict__ bias2, void* __restrict__ Cv,
               long sW, long sC)
{
    extern __shared__ __half sgm[];
    __half* As = sgm;              // [3][BUFH]
    __half* Bs = sgm + 3 * BUFH;   // [3][BUFH]

    const int z  = blockIdx.x >> 4;
    const int n0 = (blockIdx.x & 15) * 128;
    const int m0 = blockIdx.y * 128;
    const __half* Bm = Wbase + (long)z * sW;
    const float* bias = (z == 0) ? bias0 : (z == 1) ? bias1 : bias2;

    const int tid  = threadIdx.x;
    const int lane = tid & 31;
    const int wid  = tid >> 5;
    const int wm   = wid >> 2;
    const int wn   = wid & 3;
    const int g    = lane >> 2;
    const int tg   = lane & 3;

    float acc[4][4][4];
#pragma unroll
    for (int i = 0; i < 4; i++)
#pragma unroll
        for (int j = 0; j < 4; j++)
#pragma unroll
            for (int r = 0; r < 4; r++) acc[i][j][r] = 0.f;

    const uint32_t sA0 = (uint32_t)__cvta_generic_to_shared(As);
    const uint32_t sB0 = (uint32_t)__cvta_generic_to_shared(Bs);
    const uint32_t aBase = sA0 + (((wm * 64 + (lane & 15)) * PADH) + (lane >> 4) * 8) * 2;
    const uint32_t bBase = sB0 + (((wn * 32 + (lane & 7) + ((lane >> 4) << 3)) * PADH)
                                  + ((lane >> 3) & 1) * 8) * 2;

    // one BK=64 tile: A 128x64 halves, B 128x64 halves (4 cpa16/thread each)
    auto prefetch = [&](int kt, int buf) {
#pragma unroll
        for (int u = 0; u < 4; u++) {
            int id   = tid + u * 256;        // 0..1023
            int row  = id >> 3;              // 0..127
            int col8 = (id & 7) << 3;        // 0,8,...,56
            const __half* ga = A  + (long)(m0 + row) * HID + kt * 64 + col8;
            const __half* gb = Bm + (long)(n0 + row) * HID + kt * 64 + col8;
            cpa16((uint32_t)__cvta_generic_to_shared(&As[buf * BUFH + row * PADH + col8]), ga);
            cpa16((uint32_t)__cvta_generic_to_shared(&Bs[buf * BUFH + row * PADH + col8]), gb);
        }
        asm volatile("cp.async.commit_group;");
    };

    prefetch(0, 0);
    prefetch(1, 1);

    const int nK = HID >> 6;   // 32 tiles
    int buf = 0, pbuf = 2;
    for (int t = 0; t < nK; t++) {
        if (t + 1 < nK) asm volatile("cp.async.wait_group 1;");
        else            asm volatile("cp.async.wait_group 0;");
        __syncthreads();

        if (t + 2 < nK) prefetch(t + 2, pbuf);

        const uint32_t bufOff = (uint32_t)(buf * BUFH * 2);
#pragma unroll
        for (int k0 = 0; k0 < 64; k0 += 16) {
            uint32_t af[4][4], bf[4][2];
            const uint32_t ak = aBase + bufOff + k0 * 2;
            const uint32_t bk = bBase + bufOff + k0 * 2;
#pragma unroll
            for (int mi = 0; mi < 4; mi++)
                LDSM4(af[mi][0], af[mi][1], af[mi][2], af[mi][3],
                      ak + (uint32_t)(mi * 16 * PADH * 2));
#pragma unroll
            for (int p = 0; p < 2; p++)
                LDSM4(bf[2*p][0], bf[2*p][1], bf[2*p+1][0], bf[2*p+1][1],
                      bk + (uint32_t)(p * 16 * PADH * 2));
#pragma unroll
            for (int mi = 0; mi < 4; mi++)
#pragma unroll
                for (int ni = 0; ni < 4; ni++)
                    MMA(acc[mi][ni], af[mi][0], af[mi][1], af[mi][2], af[mi][3],
                        bf[ni][0], bf[ni][1]);
        }
        buf  = (buf  == 2) ? 0 : buf  + 1;
        pbuf = (pbuf == 2) ? 0 : pbuf + 1;
    }

    const long cOff = (long)z * sC;
#pragma unroll
    for (int mi = 0; mi < 4; mi++) {
#pragma unroll
        for (int ni = 0; ni < 4; ni++) {
            int row = m0 + wm * 64 + mi * 16 + g;
            int col = n0 + wn * 32 + ni * 8 + 2 * tg;
            float b0 = bias[col], b1 = bias[col + 1];
            float v00 = acc[mi][ni][0] + b0;
            float v01 = acc[mi][ni][1] + b1;
            float v10 = acc[mi][ni][2] + b0;
            float v11 = acc[mi][ni][3] + b1;
            if (OUT_HALF) {
                __half* C = (__half*)Cv + cOff;
                *(__half2*)(C + (long)row * HID + col)       = __floats2half2_rn(v00, v01);
                *(__half2*)(C + (long)(row + 8) * HID + col) = __floats2half2_rn(v10, v11);
            } else {
                float* C = (float*)Cv + cOff;
                *(float2*)(C + (long)row * HID + col)       = make_float2(v00, v01);
                *(float2*)(C + (long)(row + 8) * HID + col) = make_float2(v10, v11);
            }
        }
    }
}

// ---------------- fused attention, direct load from g_qkv --------------------
#define PADQ 72
#define PADK 136
#define PADV 136
#define ATT_SMEM ((256*PADQ + 256*PADK + 256*PADV) * 2)   // 176128

__global__ __launch_bounds__(256, 1)
void attn_fused(const __half* __restrict__ qkv, __half* __restrict__ ca)
{
    extern __shared__ __half smn[];
    const int t = blockIdx.y, mh = blockIdx.x;
    const int b = t >> 8, h = (t >> 4) & 15, n = t & 15;
    const int tid = threadIdx.x, lane = tid & 31, w = tid >> 5;
    const int jq = w >> 2, q = w & 3;

    const long rowbase = (long)(b * S_ + n * 256) * HID;
    const __half* qg = qkv + rowbase + h * 128 + mh * 64;
    const __half* kg = qkv + (long)MTOK * HID + rowbase + h * 128;
    const __half* vg = qkv + 2 * (long)MTOK * HID + rowbase + h * 128;

    const uint32_t qsu = (uint32_t)__cvta_generic_to_shared(smn);
    const uint32_t ksu = qsu + 256 * PADQ * 2;
    const uint32_t vsu = ksu + 256 * PADK * 2;

#pragma unroll
    for (int u = 0; u < 8; u++) {
        int id = tid + u * 256, row = id >> 3, seg = id & 7;
        cpa16(qsu + (row * PADQ + seg * 8) * 2, qg + (long)row * HID + seg * 8);
    }
#pragma unroll
    for (int u = 0; u < 8; u++) {
        int id = tid + u * 256, rr = id >> 4, seg = id & 15;
        int row = (rr & 63) + (rr >> 6) * 128;
        cpa16(ksu + (row * PADK + seg * 8) * 2, kg + (long)row * HID + seg * 8);
    }
    asm volatile("cp.async.commit_group;");
#pragma unroll
    for (int u = 0; u < 8; u++) {
        int id = tid + u * 256, rr = id >> 4, seg = id & 15;
        int row = 64 + (rr & 63) + (rr >> 6) * 128;
        cpa16(ksu + (row * PADK + seg * 8) * 2, kg + (long)row * HID + seg * 8);
    }
    asm volatile("cp.async.commit_group;");
#pragma unroll
    for (int u = 0; u < 16; u++) {
        int id = tid + u * 256, row = id >> 4, seg = id & 15;
        cpa16(vsu + (row * PADV + seg * 8) * 2, vg + (long)row * HID + seg * 8);
    }
    asm volatile("cp.async.commit_group;");

    const uint32_t aB = qsu + (((jq * 128 + (lane & 7) + ((lane >> 4) & 1) * 8) * PADQ)
                               + q * 16 + ((lane >> 3) & 1) * 8) * 2;
    const uint32_t kB = ksu + ((((lane & 7) + ((lane >> 3) & 1) * 8) * PADK)
                               + (lane >> 4) * 8) * 2;
    const uint32_t vB = vsu + ((((lane & 7) + ((lane >> 4) & 1) * 8) * PADV)
                               + ((lane >> 3) & 1) * 8) * 2;

    float acc[32][4];
#pragma unroll
    for (int i = 0; i < 32; i++)
        acc[i][0] = acc[i][1] = acc[i][2] = acc[i][3] = 0.f;

    asm volatile("cp.async.wait_group 2;");
    __syncthreads();

    uint32_t qa[8][4];
#pragma unroll
    for (int kk = 0; kk < 8; kk++)
        LDSM4T(qa[kk][0], qa[kk][1], qa[kk][2], qa[kk][3],
               aB + (uint32_t)(kk * 16 * PADQ * 2));

#pragma unroll
    for (int kk = 0; kk < 8; kk++) {
        if (kk == 4) { asm volatile("cp.async.wait_group 1;"); __syncthreads(); }
#pragma unroll
        for (int jk = 0; jk < 2; jk++) {
#pragma unroll
            for (int p = 0; p < 8; p++) {
                uint32_t b0, b1, b2, b3;
                LDSM4T(b0, b1, b2, b3,
                       kB + (uint32_t)(((jk * 128 + kk * 16) * PADK + p * 16) * 2));
                MMA(acc[jk*16 + 2*p],     qa[kk][0], qa[kk][1], qa[kk][2], qa[kk][3], b0, b1);
                MMA(acc[jk*16 + 2*p + 1], qa[kk][0], qa[kk][1], qa[kk][2], qa[kk][3], b2, b3);
            }
        }
    }

    float mx0 = -1e30f, mx1 = -1e30f;
#pragma unroll
    for (int i = 0; i < 32; i++) {
        mx0 = fmaxf(mx0, fmaxf(acc[i][0], acc[i][1]));
        mx1 = fmaxf(mx1, fmaxf(acc[i][2], acc[i][3]));
    }
    mx0 = fmaxf(mx0, __shfl_xor_sync(~0u, mx0, 1));
    mx0 = fmaxf(mx0, __shfl_xor_sync(~0u, mx0, 2));
    mx1 = fmaxf(mx1, __shfl_xor_sync(~0u, mx1, 1));
    mx1 = fmaxf(mx1, __shfl_xor_sync(~0u, mx1, 2));
    float s0 = 0.f, s1 = 0.f;
#pragma unroll
    for (int i = 0; i < 32; i++) {
        acc[i][0] = __expf((acc[i][0] - mx0) * SCALE);
        acc[i][1] = __expf((acc[i][1] - mx0) * SCALE);
        acc[i][2] = __expf((acc[i][2] - mx1) * SCALE);
        acc[i][3] = __expf((acc[i][3] - mx1) * SCALE);
        s0 += acc[i][0] + acc[i][1];
        s1 += acc[i][2] + acc[i][3];
    }
    s0 += __shfl_xor_sync(~0u, s0, 1); s0 += __shfl_xor_sync(~0u, s0, 2);
    s1 += __shfl_xor_sync(~0u, s1, 1); s1 += __shfl_xor_sync(~0u, s1, 2);
    const float inv0 = 1.f / s0, inv1 = 1.f / s1;

    asm volatile("cp.async.wait_group 0;");
    __syncthreads();

    float o[16][4];
#pragma unroll
    for (int i = 0; i < 16; i++)
        o[i][0] = o[i][1] = o[i][2] = o[i][3] = 0.f;

#pragma unroll
    for (int jk = 0; jk < 2; jk++) {
#pragma unroll
        for (int kk2 = 0; kk2 < 8; kk2++) {
            const int t0 = jk * 16 + 2 * kk2, t1 = t0 + 1;
            uint32_t a0 = packh2(acc[t0][0] * inv0, acc[t0][1] * inv0);
            uint32_t a1 = packh2(acc[t0][2] * inv1, acc[t0][3] * inv1);
            uint32_t a2 = packh2(acc[t1][0] * inv0, acc[t1][1] * inv0);
            uint32_t a3 = packh2(acc[t1][2] * inv1, acc[t1][3] * inv1);
#pragma unroll
            for (int p2 = 0; p2 < 8; p2++) {
                uint32_t b0, b1, b2, b3;
                LDSM4(b0, b1, b2, b3,
                      vB + (uint32_t)((((jk * 128 + p2 * 16) * PADV) + kk2 * 16) * 2));
                MMA(o[2*p2],     a0, a1, a2, a3, b0, b1);
                MMA(o[2*p2 + 1], a0, a1, a2, a3, b2, b3);
            }
        }
    }

    const int g = lane >> 2, tg = lane & 3;
    const int p2row = 2 * (mh * 64 + q * 16 + g) + jq;
    __half* cbase = ca + ((long)(b * 4096 + h * 256)) * HID + n * 128;
#pragma unroll
    for (int ni = 0; ni < 16; ni++) {
        int d2 = ni * 8 + 2 * tg;
        *(__half2*)(cbase + (long)p2row * HID + d2)        = __floats2half2_rn(o[ni][0], o[ni][1]);
        *(__half2*)(cbase + (long)(p2row + 16) * HID + d2) = __floats2half2_rn(o[ni][2], o[ni][3]);
    }
}

// ---------------- fused f32->f16 conversion of X + all weights ---------------
#define XN4 ((long)MTOK * HID / 4)
#define WN4 ((long)HID * HID / 4)
__global__ void conv_all(const float* __restrict__ X,
                         const float* __restrict__ W0, const float* __restrict__ W1,
                         const float* __restrict__ W2, const float* __restrict__ W3,
                         __half* __restrict__ xh, __half* __restrict__ wh)
{
    long i = (long)blockIdx.x * 256 + threadIdx.x;
    const float* src;
    __half* dst;
    long idx;
    if (i < XN4) {
        src = X; dst = xh; idx = i;
    } else {
        long j = i - XN4;
        int wsel = (int)(j / WN4);
        src = (wsel == 0) ? W0 : (wsel == 1) ? W1 : (wsel == 2) ? W2 : W3;
        dst = wh + (long)wsel * (WN4 * 4);
        idx = j - (long)wsel * WN4;
    }
    float4 v = ((const float4*)src)[idx];
    ((__half2*)dst)[2 * idx]     = __floats2half2_rn(v.x, v.y);
    ((__half2*)dst)[2 * idx + 1] = __floats2half2_rn(v.z, v.w);
}

// ---------------- launch -------------------------------------------------------
extern "C" void kernel_launch(void* const* d_in, const int* in_sizes, int n_in,
                              void* d_out, int out_size)
{
    const float* X  = (const float*)d_in[0];
    const float* Wq = (const float*)d_in[1];
    const float* bq = (const float*)d_in[2];
    const float* Wk = (const float*)d_in[3];
    const float* bk = (const float*)d_in[4];
    const float* Wv = (const float*)d_in[5];
    const float* bv = (const float*)d_in[6];
    const float* Wo = (const float*)d_in[7];
    const float* bo = (const float*)d_in[8];
    float* out = (float*)d_out;

    __half *xh, *wh, *qkv, *ca;
    cudaGetSymbolAddress((void**)&xh,  g_xh);
    cudaGetSymbolAddress((void**)&wh,  g_wh);
    cudaGetSymbolAddress((void**)&qkv, g_qkv);
    cudaGetSymbolAddress((void**)&ca,  g_ca);

    cudaFuncSetAttribute(attn_fused, cudaFuncAttributeMaxDynamicSharedMemorySize, ATT_SMEM);
    cudaFuncSetAttribute(gemm_fp16<true>,  cudaFuncAttributeMaxDynamicSharedMemorySize, GEMM_SMEM);
    cudaFuncSetAttribute(gemm_fp16<false>, cudaFuncAttributeMaxDynamicSharedMemorySize, GEMM_SMEM);

    const long WSZ = (long)HID * HID;
    const long TOT4 = XN4 + 4 * WN4;

    conv_all<<<(int)((TOT4 + 255) / 256), 256>>>(X, Wq, Wk, Wv, Wo, xh, wh);

    gemm_fp16<true><<<dim3(48, 128), 256, GEMM_SMEM>>>(xh, wh, bq, bk, bv, qkv,
                                                       WSZ, (long)MTOK * HID);

    attn_fused<<<dim3(2, NT), 256, ATT_SMEM>>>(qkv, ca);

    gemm_fp16<false><<<dim3(16, 128), 256, GEMM_SMEM>>>(ca, wh + 3 * WSZ, bo, bo, bo, out,
                                                        0, 0);
}